// round 12
// baseline (speedup 1.0000x reference)
#include <cuda_runtime.h>
#include <cuda_bf16.h>
#include <mma.h>
#include <cstdint>

using namespace nvcuda;

// ---------------- problem constants ----------------
#define BATCH 4
#define SEQ 8192
#define DM 1024
#define NH 16
#define HD 64
#define NCHUNK 32
#define MTOT (BATCH * SEQ) // 32768

// ---------------- scratch (device globals; no allocs) ----------------
__device__ float g_q[MTOT * DM];
__device__ float g_k[MTOT * DM];
__device__ float g_v[MTOT * DM];
__device__ __nv_bfloat16 g_ah[MTOT * DM]; // hi split of x, later of attn-out
__device__ __nv_bfloat16 g_al[MTOT * DM]; // lo split
__device__ __nv_bfloat16 g_wh[4 * DM * DM]; // transposed weights hi (q,k,v,o)
__device__ __nv_bfloat16 g_wl[4 * DM * DM]; // transposed weights lo

__device__ __forceinline__ void split1(float x, __nv_bfloat16& h, __nv_bfloat16& l) {
    h = __float2bfloat16_rn(x);
    l = __float2bfloat16_rn(x - __bfloat162float(h));
}

// ===========================================================================
// prep: split fp32 -> bf16 hi/lo  (R4-exact)
// ===========================================================================
__global__ __launch_bounds__(256) void splitx_kernel(
    const float4* __restrict__ in, __nv_bfloat162* __restrict__ h,
    __nv_bfloat162* __restrict__ l)
{
    size_t i = (size_t)blockIdx.x * 256 + threadIdx.x;
    float4 v = in[i];
    __nv_bfloat16 h0, h1, h2, h3, l0, l1, l2, l3;
    split1(v.x, h0, l0); split1(v.y, h1, l1);
    split1(v.z, h2, l2); split1(v.w, h3, l3);
    __nv_bfloat162 a; a.x = h0; a.y = h1;
    __nv_bfloat162 b; b.x = h2; b.y = h3;
    __nv_bfloat162 c; c.x = l0; c.y = l1;
    __nv_bfloat162 d; d.x = l2; d.y = l3;
    h[2 * i] = a; h[2 * i + 1] = b;
    l[2 * i] = c; l[2 * i + 1] = d;
}

// ===========================================================================
// prep: W[K,N] fp32 -> Wt[N,K] bf16 hi/lo (transpose + split)  (R4-exact,
// one launch per weight matrix)
// ===========================================================================
__global__ __launch_bounds__(256) void wtrans_kernel(
    const float* __restrict__ W, __nv_bfloat16* __restrict__ th,
    __nv_bfloat16* __restrict__ tl)
{
    __shared__ float tile[32][33];
    const int n0 = blockIdx.x * 32, k0 = blockIdx.y * 32;
    const int tx = threadIdx.x, ty = threadIdx.y;
    for (int r = ty; r < 32; r += 8)
        tile[r][tx] = W[(size_t)(k0 + r) * DM + n0 + tx];
    __syncthreads();
    for (int r = ty; r < 32; r += 8) {
        float v = tile[tx][r];
        __nv_bfloat16 h, l;
        split1(v, h, l);
        size_t o = (size_t)(n0 + r) * DM + k0 + tx;
        th[o] = h;
        tl[o] = l;
    }
}

// ===========================================================================
// GEMM: R11 version — best PROFILED per-launch config:
// tile 64x128, BK=64, 256 threads, warp grid 2x4, warp tile 32x32,
// 128 regs @ __launch_bounds__(256,2) -> 2 CTAs/SM (occ 24.5%, 693us,
// tensor 49% measured). Sync batched LDG->STS, stride-72 smem.
// ===========================================================================
#define BKC 64
#define NCH2 (DM / BKC) // 16
#define SSTRIDE 72
#define GEMM_SMEM ((64 + 64 + 128 + 128) * SSTRIDE * 2) // 55296 B

__global__ __launch_bounds__(256, 2) void gemm_tc(
    const __nv_bfloat16* __restrict__ Ahg, const __nv_bfloat16* __restrict__ Alg,
    const __nv_bfloat16* __restrict__ Bhg, const __nv_bfloat16* __restrict__ Blg,
    float* __restrict__ C)
{
    extern __shared__ char smem[];
    __nv_bfloat16* As_h = reinterpret_cast<__nv_bfloat16*>(smem);
    __nv_bfloat16* As_l = As_h + 64 * SSTRIDE;
    __nv_bfloat16* Bs_h = As_l + 64 * SSTRIDE;
    __nv_bfloat16* Bs_l = Bs_h + 128 * SSTRIDE;

    const int tid = threadIdx.x;
    const int wid = tid >> 5;
    const int wm = wid >> 2; // 0..1 -> 32-row block
    const int wn = wid & 3;  // 0..3 -> 32-col block
    const int bm = blockIdx.y * 64, bn = blockIdx.x * 128;

    const __nv_bfloat16* pAh = Ahg + (size_t)bm * DM;
    const __nv_bfloat16* pAl = Alg + (size_t)bm * DM;
    const __nv_bfloat16* pBh = Bhg + (size_t)bn * DM;
    const __nv_bfloat16* pBl = Blg + (size_t)bn * DM;

    wmma::fragment<wmma::accumulator, 16, 16, 16, float> acc[2][2];
#pragma unroll
    for (int i = 0; i < 2; i++)
#pragma unroll
        for (int j = 0; j < 2; j++)
            wmma::fill_fragment(acc[i][j], 0.0f);

#pragma unroll 1
    for (int c = 0; c < NCH2; c++) {
        const int kc = c * BKC;
        // ---- sync load: 3072 16B units, 12 per thread ----
#pragma unroll
        for (int p = 0; p < 12; p++) {
            const __nv_bfloat16* src;
            __nv_bfloat16* dst;
            int local;
            if (p < 2)      { src = pAh; dst = As_h; local = p * 256 + tid; }
            else if (p < 4) { src = pAl; dst = As_l; local = (p - 2) * 256 + tid; }
            else if (p < 8) { src = pBh; dst = Bs_h; local = (p - 4) * 256 + tid; }
            else            { src = pBl; dst = Bs_l; local = (p - 8) * 256 + tid; }
            const int row = local >> 3, u = local & 7;
            uint4 val = *reinterpret_cast<const uint4*>(
                src + (size_t)row * DM + kc + u * 8);
            *reinterpret_cast<uint4*>(dst + row * SSTRIDE + u * 8) = val;
        }
        __syncthreads();

#pragma unroll
        for (int ks = 0; ks < 4; ks++) {
            wmma::fragment<wmma::matrix_a, 16, 16, 16, __nv_bfloat16, wmma::row_major> ah[2];
            wmma::fragment<wmma::matrix_b, 16, 16, 16, __nv_bfloat16, wmma::col_major> bh[2];
#pragma unroll
            for (int i = 0; i < 2; i++)
                wmma::load_matrix_sync(ah[i], As_h + (wm * 32 + i * 16) * SSTRIDE + ks * 16, SSTRIDE);
#pragma unroll
            for (int j = 0; j < 2; j++)
                wmma::load_matrix_sync(bh[j], Bs_h + (wn * 32 + j * 16) * SSTRIDE + ks * 16, SSTRIDE);
            // hh
#pragma unroll
            for (int i = 0; i < 2; i++)
#pragma unroll
                for (int j = 0; j < 2; j++)
                    wmma::mma_sync(acc[i][j], ah[i], bh[j], acc[i][j]);
            // lh: Al x Bh (al transient)
            {
                wmma::fragment<wmma::matrix_a, 16, 16, 16, __nv_bfloat16, wmma::row_major> al[2];
#pragma unroll
                for (int i = 0; i < 2; i++)
                    wmma::load_matrix_sync(al[i], As_l + (wm * 32 + i * 16) * SSTRIDE + ks * 16, SSTRIDE);
#pragma unroll
                for (int i = 0; i < 2; i++)
#pragma unroll
                    for (int j = 0; j < 2; j++)
                        wmma::mma_sync(acc[i][j], al[i], bh[j], acc[i][j]);
            }
            // hl: Ah x Bl (bl transient)
            {
                wmma::fragment<wmma::matrix_b, 16, 16, 16, __nv_bfloat16, wmma::col_major> bl[2];
#pragma unroll
                for (int j = 0; j < 2; j++)
                    wmma::load_matrix_sync(bl[j], Bs_l + (wn * 32 + j * 16) * SSTRIDE + ks * 16, SSTRIDE);
#pragma unroll
                for (int i = 0; i < 2; i++)
#pragma unroll
                    for (int j = 0; j < 2; j++)
                        wmma::mma_sync(acc[i][j], ah[i], bl[j], acc[i][j]);
            }
        }
        __syncthreads();
    }

#pragma unroll
    for (int i = 0; i < 2; i++)
#pragma unroll
        for (int j = 0; j < 2; j++)
            wmma::store_matrix_sync(
                C + (size_t)(bm + wm * 32 + i * 16) * DM + bn + wn * 32 + j * 16,
                acc[i][j], DM, wmma::mem_row_major);
}

// ===========================================================================
// Chunked local attention: R4-exact (116KB smem, 128 threads).
// ===========================================================================
#define ATTN_SMEM_FLOATS (64 * 65 + 128 * 65 + 128 * 65 + 64 * 130)
#define ATTN_SMEM_BYTES (ATTN_SMEM_FLOATS * 4)

__global__ __launch_bounds__(128) void attn_kernel(
    const float* __restrict__ q, const float* __restrict__ k,
    const float* __restrict__ v, __nv_bfloat16* __restrict__ oh,
    __nv_bfloat16* __restrict__ ol)
{
    extern __shared__ float smemf[];
    float* Qs = smemf;            // [64][65]
    float* Ks = Qs + 64 * 65;     // [128][65]
    float* Vs = Ks + 128 * 65;    // [128][65]
    float* Ss = Vs + 128 * 65;    // [64][130]

    const int bid = blockIdx.x;
    const int rtile = bid & 3;
    const int head = (bid >> 2) & 15;
    const int chunk = (bid >> 6) & (NCHUNK - 1);
    const int b = bid >> 11;

    const int tid = threadIdx.x;
    const int c0 = rtile * 64 - 64;
    const size_t base = ((size_t)(b * SEQ + chunk * 256)) * DM + head * HD;

    for (int idx = tid; idx < 64 * 16; idx += 128) {
        int row = idx >> 4;
        int c = (idx & 15) << 2;
        float4 val = *reinterpret_cast<const float4*>(
            q + base + (size_t)(rtile * 64 + row) * DM + c);
        float* dst = Qs + row * 65 + c;
        dst[0] = val.x; dst[1] = val.y; dst[2] = val.z; dst[3] = val.w;
    }
    for (int idx = tid; idx < 128 * 16; idx += 128) {
        int row = idx >> 4;
        int c = (idx & 15) << 2;
        int jc = c0 + row;
        float4 kv = make_float4(0.f, 0.f, 0.f, 0.f);
        float4 vv = make_float4(0.f, 0.f, 0.f, 0.f);
        if (jc >= 0) {
            kv = *reinterpret_cast<const float4*>(k + base + (size_t)jc * DM + c);
            vv = *reinterpret_cast<const float4*>(v + base + (size_t)jc * DM + c);
        }
        float* dk = Ks + row * 65 + c;
        dk[0] = kv.x; dk[1] = kv.y; dk[2] = kv.z; dk[3] = kv.w;
        float* dv = Vs + row * 65 + c;
        dv[0] = vv.x; dv[1] = vv.y; dv[2] = vv.z; dv[3] = vv.w;
    }
    __syncthreads();

    {
        const int rg = tid >> 3;
        const int cg = tid & 7;
        float acc[4][16];
#pragma unroll
        for (int r = 0; r < 4; r++)
#pragma unroll
            for (int jj = 0; jj < 16; jj++) acc[r][jj] = 0.f;

        for (int d = 0; d < 64; d++) {
            float qv0 = Qs[rg * 65 + d];
            float qv1 = Qs[(rg + 16) * 65 + d];
            float qv2 = Qs[(rg + 32) * 65 + d];
            float qv3 = Qs[(rg + 48) * 65 + d];
#pragma unroll
            for (int jj = 0; jj < 16; jj++) {
                float kv = Ks[(cg + 8 * jj) * 65 + d];
                acc[0][jj] += qv0 * kv;
                acc[1][jj] += qv1 * kv;
                acc[2][jj] += qv2 * kv;
                acc[3][jj] += qv3 * kv;
            }
        }
        const float scale = 0.125f;
#pragma unroll
        for (int r = 0; r < 4; r++)
#pragma unroll
            for (int jj = 0; jj < 16; jj++)
                Ss[(rg + 16 * r) * 130 + cg + 8 * jj] = acc[r][jj] * scale;
    }
    __syncthreads();

    {
        const int i = tid >> 1;
        const int half = tid & 1;
        const int lo = (rtile == 0) ? 64 : i;
        const int hi = i + 64;
        float* row = Ss + i * 130 + half * 64;
        const int jbase = half * 64;

        float m = -1e30f;
#pragma unroll
        for (int jj = 0; jj < 64; jj++) {
            int j = jbase + jj;
            if (j >= lo && j <= hi) m = fmaxf(m, row[jj]);
        }
        m = fmaxf(m, __shfl_xor_sync(0xffffffffu, m, 1));

        float s = 0.f;
#pragma unroll
        for (int jj = 0; jj < 64; jj++) {
            int j = jbase + jj;
            float e = 0.f;
            if (j >= lo && j <= hi) {
                e = __expf(row[jj] - m);
                s += e;
            }
            row[jj] = e;
        }
        s += __shfl_xor_sync(0xffffffffu, s, 1);
        float inv = 1.0f / s;
#pragma unroll
        for (int jj = 0; jj < 64; jj++) row[jj] *= inv;
    }
    __syncthreads();

    {
        const int rg = tid >> 2;
        const int cg = tid & 3;
        float acc0[16], acc1[16];
#pragma unroll
        for (int dd = 0; dd < 16; dd++) { acc0[dd] = 0.f; acc1[dd] = 0.f; }

        for (int j = 0; j < 128; j++) {
            float p0 = Ss[rg * 130 + j];
            float p1 = Ss[(rg + 32) * 130 + j];
#pragma unroll
            for (int dd = 0; dd < 16; dd++) {
                float vv = Vs[j * 65 + cg * 16 + dd];
                acc0[dd] += p0 * vv;
                acc1[dd] += p1 * vv;
            }
        }
#pragma unroll
        for (int r = 0; r < 2; r++) {
            const float* accp = r ? acc1 : acc0;
            size_t off = base + (size_t)(rtile * 64 + rg + 32 * r) * DM + cg * 16;
#pragma unroll
            for (int d2 = 0; d2 < 8; d2++) {
                __nv_bfloat16 h0, h1, l0, l1;
                split1(accp[d2 * 2 + 0], h0, l0);
                split1(accp[d2 * 2 + 1], h1, l1);
                __nv_bfloat162 hp; hp.x = h0; hp.y = h1;
                __nv_bfloat162 lp; lp.x = l0; lp.y = l1;
                *reinterpret_cast<__nv_bfloat162*>(oh + off + d2 * 2) = hp;
                *reinterpret_cast<__nv_bfloat162*>(ol + off + d2 * 2) = lp;
            }
        }
    }
}

// ===========================================================================
// kernel_launch  (R4 layout: separate wtrans + separate GEMM launches)
// ===========================================================================
extern "C" void kernel_launch(void* const* d_in, const int* in_sizes, int n_in,
                              void* d_out, int out_size)
{
    (void)in_sizes; (void)n_in; (void)out_size;
    const float* x  = (const float*)d_in[0];
    const float* Wq = (const float*)d_in[1];
    const float* Wk = (const float*)d_in[2];
    const float* Wv = (const float*)d_in[3];
    const float* Wo = (const float*)d_in[4];
    float* out = (float*)d_out;

    float *q, *k, *v;
    __nv_bfloat16 *ah, *al, *wh, *wl;
    cudaGetSymbolAddress((void**)&q, g_q);
    cudaGetSymbolAddress((void**)&k, g_k);
    cudaGetSymbolAddress((void**)&v, g_v);
    cudaGetSymbolAddress((void**)&ah, g_ah);
    cudaGetSymbolAddress((void**)&al, g_al);
    cudaGetSymbolAddress((void**)&wh, g_wh);
    cudaGetSymbolAddress((void**)&wl, g_wl);

    cudaFuncSetAttribute(gemm_tc, cudaFuncAttributeMaxDynamicSharedMemorySize,
                         GEMM_SMEM);
    cudaFuncSetAttribute(attn_kernel, cudaFuncAttributeMaxDynamicSharedMemorySize,
                         ATTN_SMEM_BYTES);

    // 1) split x into bf16 hi/lo
    splitx_kernel<<<(MTOT * DM / 4) / 256, 256>>>(
        (const float4*)x, (__nv_bfloat162*)ah, (__nv_bfloat162*)al);

    // 2) transpose+split all four weights (R4 style: 4 launches)
    dim3 wgrid(DM / 32, DM / 32);
    dim3 wblk(32, 8);
    wtrans_kernel<<<wgrid, wblk>>>(Wq, wh + 0 * (size_t)DM * DM, wl + 0 * (size_t)DM * DM);
    wtrans_kernel<<<wgrid, wblk>>>(Wk, wh + 1 * (size_t)DM * DM, wl + 1 * (size_t)DM * DM);
    wtrans_kernel<<<wgrid, wblk>>>(Wv, wh + 2 * (size_t)DM * DM, wl + 2 * (size_t)DM * DM);
    wtrans_kernel<<<wgrid, wblk>>>(Wo, wh + 3 * (size_t)DM * DM, wl + 3 * (size_t)DM * DM);

    // 3) Q/K/V projections (separate launches)
    dim3 ggrid(DM / 128, MTOT / 64); // (8, 512)
    gemm_tc<<<ggrid, 256, GEMM_SMEM>>>(ah, al, wh + 0 * (size_t)DM * DM, wl + 0 * (size_t)DM * DM, q);
    gemm_tc<<<ggrid, 256, GEMM_SMEM>>>(ah, al, wh + 1 * (size_t)DM * DM, wl + 1 * (size_t)DM * DM, k);
    gemm_tc<<<ggrid, 256, GEMM_SMEM>>>(ah, al, wh + 2 * (size_t)DM * DM, wl + 2 * (size_t)DM * DM, v);

    // 4) attention (writes bf16 hi/lo into ah/al)
    attn_kernel<<<BATCH * NCHUNK * NH * 4, 128, ATTN_SMEM_BYTES>>>(q, k, v, ah, al);

    // 5) output projection
    gemm_tc<<<ggrid, 256, GEMM_SMEM>>>(ah, al, wh + 3 * (size_t)DM * DM, wl + 3 * (size_t)DM * DM, out);
}

// round 13
// speedup vs baseline: 1.3827x; 1.3827x over previous
#include <cuda_runtime.h>
#include <cuda_bf16.h>
#include <mma.h>
#include <cstdint>

using namespace nvcuda;

// ---------------- problem constants ----------------
#define BATCH 4
#define SEQ 8192
#define DM 1024
#define NH 16
#define HD 64
#define NCHUNK 32
#define MTOT (BATCH * SEQ) // 32768

// ---------------- scratch (device globals; no allocs) ----------------
__device__ float g_q[MTOT * DM];
__device__ float g_k[MTOT * DM];
__device__ float g_v[MTOT * DM];
__device__ __nv_bfloat16 g_ah[MTOT * DM]; // hi split of x, later of attn-out
__device__ __nv_bfloat16 g_al[MTOT * DM]; // lo split
__device__ __nv_bfloat16 g_wh[4 * DM * DM]; // transposed weights hi (q,k,v,o)
__device__ __nv_bfloat16 g_wl[4 * DM * DM]; // transposed weights lo

__device__ __forceinline__ void split1(float x, __nv_bfloat16& h, __nv_bfloat16& l) {
    h = __float2bfloat16_rn(x);
    l = __float2bfloat16_rn(x - __bfloat162float(h));
}

// ===========================================================================
// prep: split fp32 -> bf16 hi/lo
// ===========================================================================
__global__ __launch_bounds__(256) void splitx_kernel(
    const float4* __restrict__ in, __nv_bfloat162* __restrict__ h,
    __nv_bfloat162* __restrict__ l)
{
    size_t i = (size_t)blockIdx.x * 256 + threadIdx.x;
    float4 v = in[i];
    __nv_bfloat16 h0, h1, h2, h3, l0, l1, l2, l3;
    split1(v.x, h0, l0); split1(v.y, h1, l1);
    split1(v.z, h2, l2); split1(v.w, h3, l3);
    __nv_bfloat162 a; a.x = h0; a.y = h1;
    __nv_bfloat162 b; b.x = h2; b.y = h3;
    __nv_bfloat162 c; c.x = l0; c.y = l1;
    __nv_bfloat162 d; d.x = l2; d.y = l3;
    h[2 * i] = a; h[2 * i + 1] = b;
    l[2 * i] = c; l[2 * i + 1] = d;
}

// ===========================================================================
// prep: W[K,N] fp32 -> Wt[N,K] bf16 hi/lo, 4 mats in one launch (blockIdx.z)
// ===========================================================================
__global__ __launch_bounds__(256) void wtrans_kernel(
    const float* __restrict__ W0, const float* __restrict__ W1,
    const float* __restrict__ W2, const float* __restrict__ W3,
    __nv_bfloat16* __restrict__ th, __nv_bfloat16* __restrict__ tl)
{
    __shared__ float tile[32][33];
    const int mat = blockIdx.z;
    const float* W = (mat == 0) ? W0 : (mat == 1) ? W1 : (mat == 2) ? W2 : W3;
    __nv_bfloat16* thm = th + (size_t)mat * DM * DM;
    __nv_bfloat16* tlm = tl + (size_t)mat * DM * DM;

    const int n0 = blockIdx.x * 32, k0 = blockIdx.y * 32;
    const int tx = threadIdx.x, ty = threadIdx.y;
    for (int r = ty; r < 32; r += 8)
        tile[r][tx] = W[(size_t)(k0 + r) * DM + n0 + tx];
    __syncthreads();
    for (int r = ty; r < 32; r += 8) {
        float v = tile[tx][r];
        __nv_bfloat16 h, l;
        split1(v, h, l);
        size_t o = (size_t)(n0 + r) * DM + k0 + tx;
        thm[o] = h;
        tlm[o] = l;
    }
}

// ===========================================================================
// GEMM: R11 (best profiled: 693us, regs=128, occ 24.5%).
// Tile 64x128, BK=64, 256 threads, warp tile 32x32, sync LDG->STS.
// ===========================================================================
#define BKC 64
#define NCH2 (DM / BKC) // 16
#define SSTRIDE 72
#define GEMM_SMEM ((64 + 64 + 128 + 128) * SSTRIDE * 2) // 55296 B

__global__ __launch_bounds__(256, 2) void gemm_tc(
    const __nv_bfloat16* __restrict__ Ahg, const __nv_bfloat16* __restrict__ Alg,
    const __nv_bfloat16* __restrict__ Bhg, const __nv_bfloat16* __restrict__ Blg,
    float* __restrict__ C)
{
    extern __shared__ char smem[];
    __nv_bfloat16* As_h = reinterpret_cast<__nv_bfloat16*>(smem);
    __nv_bfloat16* As_l = As_h + 64 * SSTRIDE;
    __nv_bfloat16* Bs_h = As_l + 64 * SSTRIDE;
    __nv_bfloat16* Bs_l = Bs_h + 128 * SSTRIDE;

    const int tid = threadIdx.x;
    const int wid = tid >> 5;
    const int wm = wid >> 2;
    const int wn = wid & 3;
    const int bm = blockIdx.y * 64, bn = blockIdx.x * 128;

    const __nv_bfloat16* pAh = Ahg + (size_t)bm * DM;
    const __nv_bfloat16* pAl = Alg + (size_t)bm * DM;
    const __nv_bfloat16* pBh = Bhg + (size_t)bn * DM;
    const __nv_bfloat16* pBl = Blg + (size_t)bn * DM;

    wmma::fragment<wmma::accumulator, 16, 16, 16, float> acc[2][2];
#pragma unroll
    for (int i = 0; i < 2; i++)
#pragma unroll
        for (int j = 0; j < 2; j++)
            wmma::fill_fragment(acc[i][j], 0.0f);

#pragma unroll 1
    for (int c = 0; c < NCH2; c++) {
        const int kc = c * BKC;
#pragma unroll
        for (int p = 0; p < 12; p++) {
            const __nv_bfloat16* src;
            __nv_bfloat16* dst;
            int local;
            if (p < 2)      { src = pAh; dst = As_h; local = p * 256 + tid; }
            else if (p < 4) { src = pAl; dst = As_l; local = (p - 2) * 256 + tid; }
            else if (p < 8) { src = pBh; dst = Bs_h; local = (p - 4) * 256 + tid; }
            else            { src = pBl; dst = Bs_l; local = (p - 8) * 256 + tid; }
            const int row = local >> 3, u = local & 7;
            uint4 val = *reinterpret_cast<const uint4*>(
                src + (size_t)row * DM + kc + u * 8);
            *reinterpret_cast<uint4*>(dst + row * SSTRIDE + u * 8) = val;
        }
        __syncthreads();

#pragma unroll
        for (int ks = 0; ks < 4; ks++) {
            wmma::fragment<wmma::matrix_a, 16, 16, 16, __nv_bfloat16, wmma::row_major> ah[2];
            wmma::fragment<wmma::matrix_b, 16, 16, 16, __nv_bfloat16, wmma::col_major> bh[2];
#pragma unroll
            for (int i = 0; i < 2; i++)
                wmma::load_matrix_sync(ah[i], As_h + (wm * 32 + i * 16) * SSTRIDE + ks * 16, SSTRIDE);
#pragma unroll
            for (int j = 0; j < 2; j++)
                wmma::load_matrix_sync(bh[j], Bs_h + (wn * 32 + j * 16) * SSTRIDE + ks * 16, SSTRIDE);
#pragma unroll
            for (int i = 0; i < 2; i++)
#pragma unroll
                for (int j = 0; j < 2; j++)
                    wmma::mma_sync(acc[i][j], ah[i], bh[j], acc[i][j]);
            {
                wmma::fragment<wmma::matrix_a, 16, 16, 16, __nv_bfloat16, wmma::row_major> al[2];
#pragma unroll
                for (int i = 0; i < 2; i++)
                    wmma::load_matrix_sync(al[i], As_l + (wm * 32 + i * 16) * SSTRIDE + ks * 16, SSTRIDE);
#pragma unroll
                for (int i = 0; i < 2; i++)
#pragma unroll
                    for (int j = 0; j < 2; j++)
                        wmma::mma_sync(acc[i][j], al[i], bh[j], acc[i][j]);
            }
            {
                wmma::fragment<wmma::matrix_b, 16, 16, 16, __nv_bfloat16, wmma::col_major> bl[2];
#pragma unroll
                for (int j = 0; j < 2; j++)
                    wmma::load_matrix_sync(bl[j], Bs_l + (wn * 32 + j * 16) * SSTRIDE + ks * 16, SSTRIDE);
#pragma unroll
                for (int i = 0; i < 2; i++)
#pragma unroll
                    for (int j = 0; j < 2; j++)
                        wmma::mma_sync(acc[i][j], ah[i], bl[j], acc[i][j]);
            }
        }
        __syncthreads();
    }

#pragma unroll
    for (int i = 0; i < 2; i++)
#pragma unroll
        for (int j = 0; j < 2; j++)
            wmma::store_matrix_sync(
                C + (size_t)(bm + wm * 32 + i * 16) * DM + bn + wn * 32 + j * 16,
                acc[i][j], DM, wmma::mem_row_major);
}

// ===========================================================================
// Chunked local attention on TENSOR CORES (bf16x3 scores, bf16x2 PV),
// 256 threads, heavy smem overlay -> 92160 B -> 2 CTAs/SM.
//   region A (55296 B): Qh|Ql|Kh|Kl  ->  Ss(f32 64x132) -> Ph|Pl(64x136) -> O(f32 64x68)
//   region B (36864 B): Vh|Vl  (persistent)
// ===========================================================================
#define AT_STRIDE 72   // bf16 (144B = 9*16)
#define SS_STRIDE 132  // fp32 (528B = 33*16)
#define P_STRIDE 136   // bf16 (272B = 17*16)
#define O_STRIDE 68    // fp32 (272B = 17*16)

#define QH_OFF 0
#define QL_OFF (64 * AT_STRIDE * 2)                 // 9216
#define KH_OFF (2 * 64 * AT_STRIDE * 2)             // 18432
#define KL_OFF (KH_OFF + 128 * AT_STRIDE * 2)       // 36864
#define VH_OFF (KL_OFF + 128 * AT_STRIDE * 2)       // 55296
#define VL_OFF (VH_OFF + 128 * AT_STRIDE * 2)       // 73728
#define ATTN_SMEM_BYTES (VL_OFF + 128 * AT_STRIDE * 2) // 92160
#define PH_OFF 0
#define PL_OFF (64 * P_STRIDE * 2)                  // 17408

__global__ __launch_bounds__(256, 2) void attn_kernel(
    const float* __restrict__ q, const float* __restrict__ k,
    const float* __restrict__ v, __nv_bfloat16* __restrict__ oh,
    __nv_bfloat16* __restrict__ ol)
{
    extern __shared__ char sm[];
    __nv_bfloat16* Qh = reinterpret_cast<__nv_bfloat16*>(sm + QH_OFF);
    __nv_bfloat16* Ql = reinterpret_cast<__nv_bfloat16*>(sm + QL_OFF);
    __nv_bfloat16* Kh = reinterpret_cast<__nv_bfloat16*>(sm + KH_OFF);
    __nv_bfloat16* Kl = reinterpret_cast<__nv_bfloat16*>(sm + KL_OFF);
    __nv_bfloat16* Vh = reinterpret_cast<__nv_bfloat16*>(sm + VH_OFF);
    __nv_bfloat16* Vl = reinterpret_cast<__nv_bfloat16*>(sm + VL_OFF);
    float* Ss = reinterpret_cast<float*>(sm);            // overlay on Q/K
    __nv_bfloat16* Ph = reinterpret_cast<__nv_bfloat16*>(sm + PH_OFF);
    __nv_bfloat16* Pl = reinterpret_cast<__nv_bfloat16*>(sm + PL_OFF);
    float* Os = reinterpret_cast<float*>(sm);            // overlay (after P dead)

    const int bid = blockIdx.x;
    const int rtile = bid & 3;
    const int head = (bid >> 2) & 15;
    const int chunk = (bid >> 6) & (NCHUNK - 1);
    const int b = bid >> 11;

    const int tid = threadIdx.x;
    const int wid = tid >> 5;
    const int wm = wid >> 2; // 0..1
    const int wn = wid & 3;  // 0..3
    const int c0 = rtile * 64 - 64;
    const size_t base = ((size_t)(b * SEQ + chunk * 256)) * DM + head * HD;

    // ---- load Q (scaled by 1/8, exact) + split ----
    for (int idx = tid; idx < 64 * 16; idx += 256) {
        int row = idx >> 4;
        int c = (idx & 15) << 2;
        float4 val = *reinterpret_cast<const float4*>(
            q + base + (size_t)(rtile * 64 + row) * DM + c);
        float f[4] = {val.x * 0.125f, val.y * 0.125f, val.z * 0.125f, val.w * 0.125f};
#pragma unroll
        for (int t = 0; t < 4; t++) {
            __nv_bfloat16 h, l;
            split1(f[t], h, l);
            Qh[row * AT_STRIDE + c + t] = h;
            Ql[row * AT_STRIDE + c + t] = l;
        }
    }
    // ---- load K, V + split (zero-fill out-of-chunk rows) ----
    for (int idx = tid; idx < 128 * 16; idx += 256) {
        int row = idx >> 4;
        int c = (idx & 15) << 2;
        int jc = c0 + row;
        float4 kv = make_float4(0.f, 0.f, 0.f, 0.f);
        float4 vv = make_float4(0.f, 0.f, 0.f, 0.f);
        if (jc >= 0) {
            kv = *reinterpret_cast<const float4*>(k + base + (size_t)jc * DM + c);
            vv = *reinterpret_cast<const float4*>(v + base + (size_t)jc * DM + c);
        }
        float kf[4] = {kv.x, kv.y, kv.z, kv.w};
        float vf[4] = {vv.x, vv.y, vv.z, vv.w};
#pragma unroll
        for (int t = 0; t < 4; t++) {
            __nv_bfloat16 h, l;
            split1(kf[t], h, l);
            Kh[row * AT_STRIDE + c + t] = h;
            Kl[row * AT_STRIDE + c + t] = l;
            split1(vf[t], h, l);
            Vh[row * AT_STRIDE + c + t] = h;
            Vl[row * AT_STRIDE + c + t] = l;
        }
    }
    __syncthreads();

    // ---- S = (Q/8) @ K^T via bf16x3 WMMA; warp tile 32x32 ----
    wmma::fragment<wmma::accumulator, 16, 16, 16, float> sacc[2][2];
#pragma unroll
    for (int i = 0; i < 2; i++)
#pragma unroll
        for (int j = 0; j < 2; j++)
            wmma::fill_fragment(sacc[i][j], 0.0f);

#pragma unroll
    for (int ks = 0; ks < 4; ks++) {
        wmma::fragment<wmma::matrix_a, 16, 16, 16, __nv_bfloat16, wmma::row_major> ah[2];
        wmma::fragment<wmma::matrix_b, 16, 16, 16, __nv_bfloat16, wmma::col_major> bh[2];
#pragma unroll
        for (int i = 0; i < 2; i++)
            wmma::load_matrix_sync(ah[i], Qh + (wm * 32 + i * 16) * AT_STRIDE + ks * 16, AT_STRIDE);
#pragma unroll
        for (int j = 0; j < 2; j++)
            wmma::load_matrix_sync(bh[j], Kh + (wn * 32 + j * 16) * AT_STRIDE + ks * 16, AT_STRIDE);
#pragma unroll
        for (int i = 0; i < 2; i++)
#pragma unroll
            for (int j = 0; j < 2; j++)
                wmma::mma_sync(sacc[i][j], ah[i], bh[j], sacc[i][j]);
        {
            wmma::fragment<wmma::matrix_a, 16, 16, 16, __nv_bfloat16, wmma::row_major> al[2];
#pragma unroll
            for (int i = 0; i < 2; i++)
                wmma::load_matrix_sync(al[i], Ql + (wm * 32 + i * 16) * AT_STRIDE + ks * 16, AT_STRIDE);
#pragma unroll
            for (int i = 0; i < 2; i++)
#pragma unroll
                for (int j = 0; j < 2; j++)
                    wmma::mma_sync(sacc[i][j], al[i], bh[j], sacc[i][j]);
        }
        {
            wmma::fragment<wmma::matrix_b, 16, 16, 16, __nv_bfloat16, wmma::col_major> bl[2];
#pragma unroll
            for (int j = 0; j < 2; j++)
                wmma::load_matrix_sync(bl[j], Kl + (wn * 32 + j * 16) * AT_STRIDE + ks * 16, AT_STRIDE);
#pragma unroll
            for (int i = 0; i < 2; i++)
#pragma unroll
                for (int j = 0; j < 2; j++)
                    wmma::mma_sync(sacc[i][j], ah[i], bl[j], sacc[i][j]);
        }
    }
    __syncthreads(); // all warps done reading Q/K smem -> safe to overlay Ss

#pragma unroll
    for (int i = 0; i < 2; i++)
#pragma unroll
        for (int j = 0; j < 2; j++)
            wmma::store_matrix_sync(
                Ss + (wm * 32 + i * 16) * SS_STRIDE + wn * 32 + j * 16,
                sacc[i][j], SS_STRIDE, wmma::mem_row_major);
    __syncthreads();

    // ---- masked softmax: 4 threads per row, 32 cols each ----
    {
        const int i = tid >> 2;
        const int sub = tid & 3;
        const int lo = (rtile == 0) ? 64 : i;
        const int hi = i + 64;
        float* row = Ss + i * SS_STRIDE + sub * 32;
        const int jbase = sub * 32;

        float m = -1e30f;
#pragma unroll
        for (int jj = 0; jj < 32; jj++) {
            int j = jbase + jj;
            if (j >= lo && j <= hi) m = fmaxf(m, row[jj]);
        }
        m = fmaxf(m, __shfl_xor_sync(0xffffffffu, m, 1));
        m = fmaxf(m, __shfl_xor_sync(0xffffffffu, m, 2));

        float s = 0.f;
#pragma unroll
        for (int jj = 0; jj < 32; jj++) {
            int j = jbase + jj;
            float e = 0.f;
            if (j >= lo && j <= hi) {
                e = __expf(row[jj] - m);
                s += e;
            }
            row[jj] = e;
        }
        s += __shfl_xor_sync(0xffffffffu, s, 1);
        s += __shfl_xor_sync(0xffffffffu, s, 2);
        float inv = 1.0f / s;
#pragma unroll
        for (int jj = 0; jj < 32; jj++) row[jj] *= inv;
    }
    __syncthreads();

    // ---- convert P to bf16 hi/lo (stage through regs; Ph/Pl overlay Ss) ----
    {
        const int row = tid >> 2;
        const int jb = (tid & 3) * 32;
        float pr[32];
#pragma unroll
        for (int t = 0; t < 32; t++) pr[t] = Ss[row * SS_STRIDE + jb + t];
        __syncthreads(); // all Ss reads done -> safe to overwrite with Ph/Pl
#pragma unroll
        for (int t = 0; t < 32; t++) {
            __nv_bfloat16 h, l;
            split1(pr[t], h, l);
            Ph[row * P_STRIDE + jb + t] = h;
            Pl[row * P_STRIDE + jb + t] = l;
        }
    }
    __syncthreads();

    // ---- O = P @ V via WMMA (ph*vh + ph*vl + pl*vh); warp tile 32x16 ----
    wmma::fragment<wmma::accumulator, 16, 16, 16, float> oacc[2];
#pragma unroll
    for (int i = 0; i < 2; i++) wmma::fill_fragment(oacc[i], 0.0f);

#pragma unroll
    for (int ks = 0; ks < 8; ks++) {
        wmma::fragment<wmma::matrix_a, 16, 16, 16, __nv_bfloat16, wmma::row_major> pah[2];
        wmma::fragment<wmma::matrix_b, 16, 16, 16, __nv_bfloat16, wmma::row_major> vbh;
#pragma unroll
        for (int i = 0; i < 2; i++)
            wmma::load_matrix_sync(pah[i], Ph + (wm * 32 + i * 16) * P_STRIDE + ks * 16, P_STRIDE);
        wmma::load_matrix_sync(vbh, Vh + (ks * 16) * AT_STRIDE + wn * 16, AT_STRIDE);
#pragma unroll
        for (int i = 0; i < 2; i++)
            wmma::mma_sync(oacc[i], pah[i], vbh, oacc[i]);
        {
            wmma::fragment<wmma::matrix_b, 16, 16, 16, __nv_bfloat16, wmma::row_major> vbl;
            wmma::load_matrix_sync(vbl, Vl + (ks * 16) * AT_STRIDE + wn * 16, AT_STRIDE);
#pragma unroll
            for (int i = 0; i < 2; i++)
                wmma::mma_sync(oacc[i], pah[i], vbl, oacc[i]);
        }
        {
            wmma::fragment<wmma::matrix_a, 16, 16, 16, __nv_bfloat16, wmma::row_major> pal[2];
#pragma unroll
            for (int i = 0; i < 2; i++)
                wmma::load_matrix_sync(pal[i], Pl + (wm * 32 + i * 16) * P_STRIDE + ks * 16, P_STRIDE);
            wmma::fragment<wmma::matrix_b, 16, 16, 16, __nv_bfloat16, wmma::row_major> vbh2;
            wmma::load_matrix_sync(vbh2, Vh + (ks * 16) * AT_STRIDE + wn * 16, AT_STRIDE);
#pragma unroll
            for (int i = 0; i < 2; i++)
                wmma::mma_sync(oacc[i], pal[i], vbh2, oacc[i]);
        }
    }
    __syncthreads(); // all warps done reading Ph/Pl/V -> safe to overlay O

#pragma unroll
    for (int i = 0; i < 2; i++)
        wmma::store_matrix_sync(Os + (wm * 32 + i * 16) * O_STRIDE + wn * 16,
                                oacc[i], O_STRIDE, wmma::mem_row_major);
    __syncthreads();

    // ---- writeout: split O to bf16 hi/lo in gmem ----
    {
        const int row = tid >> 2;
        const int d0 = (tid & 3) * 16;
        size_t off = base + (size_t)(rtile * 64 + row) * DM + d0;
#pragma unroll
        for (int d2 = 0; d2 < 8; d2++) {
            float f0 = Os[row * O_STRIDE + d0 + d2 * 2 + 0];
            float f1 = Os[row * O_STRIDE + d0 + d2 * 2 + 1];
            __nv_bfloat16 h0, h1, l0, l1;
            split1(f0, h0, l0);
            split1(f1, h1, l1);
            __nv_bfloat162 hp; hp.x = h0; hp.y = h1;
            __nv_bfloat162 lp; lp.x = l0; lp.y = l1;
            *reinterpret_cast<__nv_bfloat162*>(oh + off + d2 * 2) = hp;
            *reinterpret_cast<__nv_bfloat162*>(ol + off + d2 * 2) = lp;
        }
    }
}

// ===========================================================================
// kernel_launch
// ===========================================================================
extern "C" void kernel_launch(void* const* d_in, const int* in_sizes, int n_in,
                              void* d_out, int out_size)
{
    (void)in_sizes; (void)n_in; (void)out_size;
    const float* x  = (const float*)d_in[0];
    const float* Wq = (const float*)d_in[1];
    const float* Wk = (const float*)d_in[2];
    const float* Wv = (const float*)d_in[3];
    const float* Wo = (const float*)d_in[4];
    float* out = (float*)d_out;

    float *q, *k, *v;
    __nv_bfloat16 *ah, *al, *wh, *wl;
    cudaGetSymbolAddress((void**)&q, g_q);
    cudaGetSymbolAddress((void**)&k, g_k);
    cudaGetSymbolAddress((void**)&v, g_v);
    cudaGetSymbolAddress((void**)&ah, g_ah);
    cudaGetSymbolAddress((void**)&al, g_al);
    cudaGetSymbolAddress((void**)&wh, g_wh);
    cudaGetSymbolAddress((void**)&wl, g_wl);

    cudaFuncSetAttribute(gemm_tc, cudaFuncAttributeMaxDynamicSharedMemorySize,
                         GEMM_SMEM);
    cudaFuncSetAttribute(attn_kernel, cudaFuncAttributeMaxDynamicSharedMemorySize,
                         ATTN_SMEM_BYTES);

    // 1) split x into bf16 hi/lo
    splitx_kernel<<<(MTOT * DM / 4) / 256, 256>>>(
        (const float4*)x, (__nv_bfloat162*)ah, (__nv_bfloat162*)al);

    // 2) transpose+split all four weights (one launch)
    dim3 wgrid(DM / 32, DM / 32, 4);
    dim3 wblk(32, 8);
    wtrans_kernel<<<wgrid, wblk>>>(Wq, Wk, Wv, Wo, wh, wl);

    // 3) Q/K/V projections
    dim3 ggrid(DM / 128, MTOT / 64); // (8, 512)
    gemm_tc<<<ggrid, 256, GEMM_SMEM>>>(ah, al, wh + 0 * (size_t)DM * DM, wl + 0 * (size_t)DM * DM, q);
    gemm_tc<<<ggrid, 256, GEMM_SMEM>>>(ah, al, wh + 1 * (size_t)DM * DM, wl + 1 * (size_t)DM * DM, k);
    gemm_tc<<<ggrid, 256, GEMM_SMEM>>>(ah, al, wh + 2 * (size_t)DM * DM, wl + 2 * (size_t)DM * DM, v);

    // 4) attention on tensor cores (writes bf16 hi/lo into ah/al)
    attn_kernel<<<BATCH * NCHUNK * NH * 4, 256, ATTN_SMEM_BYTES>>>(q, k, v, ah, al);

    // 5) output projection
    gemm_tc<<<ggrid, 256, GEMM_SMEM>>>(ah, al, wh + 3 * (size_t)DM * DM, wl + 3 * (size_t)DM * DM, out);
}

// round 14
// speedup vs baseline: 1.5033x; 1.0872x over previous
#include <cuda_runtime.h>
#include <cuda_bf16.h>
#include <mma.h>
#include <cstdint>

using namespace nvcuda;

// ---------------- problem constants ----------------
#define BATCH 4
#define SEQ 8192
#define DM 1024
#define NH 16
#define HD 64
#define NCHUNK 32
#define MTOT (BATCH * SEQ) // 32768

// ---------------- scratch (device globals; no allocs) ----------------
__device__ float g_q[MTOT * DM];
__device__ float g_k[MTOT * DM];
__device__ float g_v[MTOT * DM];
__device__ __nv_bfloat16 g_ah[MTOT * DM]; // hi split of x, later of attn-out
__device__ __nv_bfloat16 g_al[MTOT * DM]; // lo split
__device__ __nv_bfloat16 g_wh[4 * DM * DM]; // transposed weights hi (q,k,v,o)
__device__ __nv_bfloat16 g_wl[4 * DM * DM]; // transposed weights lo

__device__ __forceinline__ void split1(float x, __nv_bfloat16& h, __nv_bfloat16& l) {
    h = __float2bfloat16_rn(x);
    l = __float2bfloat16_rn(x - __bfloat162float(h));
}

// ===========================================================================
// prep: split fp32 -> bf16 hi/lo
// ===========================================================================
__global__ __launch_bounds__(256) void splitx_kernel(
    const float4* __restrict__ in, __nv_bfloat162* __restrict__ h,
    __nv_bfloat162* __restrict__ l)
{
    size_t i = (size_t)blockIdx.x * 256 + threadIdx.x;
    float4 v = in[i];
    __nv_bfloat16 h0, h1, h2, h3, l0, l1, l2, l3;
    split1(v.x, h0, l0); split1(v.y, h1, l1);
    split1(v.z, h2, l2); split1(v.w, h3, l3);
    __nv_bfloat162 a; a.x = h0; a.y = h1;
    __nv_bfloat162 b; b.x = h2; b.y = h3;
    __nv_bfloat162 c; c.x = l0; c.y = l1;
    __nv_bfloat162 d; d.x = l2; d.y = l3;
    h[2 * i] = a; h[2 * i + 1] = b;
    l[2 * i] = c; l[2 * i + 1] = d;
}

// ===========================================================================
// prep: W[K,N] fp32 -> Wt[N,K] bf16 hi/lo, 4 mats in one launch (blockIdx.z)
// ===========================================================================
__global__ __launch_bounds__(256) void wtrans_kernel(
    const float* __restrict__ W0, const float* __restrict__ W1,
    const float* __restrict__ W2, const float* __restrict__ W3,
    __nv_bfloat16* __restrict__ th, __nv_bfloat16* __restrict__ tl)
{
    __shared__ float tile[32][33];
    const int mat = blockIdx.z;
    const float* W = (mat == 0) ? W0 : (mat == 1) ? W1 : (mat == 2) ? W2 : W3;
    __nv_bfloat16* thm = th + (size_t)mat * DM * DM;
    __nv_bfloat16* tlm = tl + (size_t)mat * DM * DM;

    const int n0 = blockIdx.x * 32, k0 = blockIdx.y * 32;
    const int tx = threadIdx.x, ty = threadIdx.y;
    for (int r = ty; r < 32; r += 8)
        tile[r][tx] = W[(size_t)(k0 + r) * DM + n0 + tx];
    __syncthreads();
    for (int r = ty; r < 32; r += 8) {
        float v = tile[tx][r];
        __nv_bfloat16 h, l;
        split1(v, h, l);
        size_t o = (size_t)(n0 + r) * DM + k0 + tx;
        thm[o] = h;
        tlm[o] = l;
    }
}

// ===========================================================================
// GEMM: CTA tile 64x256, BK=64, 256 threads, warp grid 2x4,
// WARP TILE 32x64 (acc[2][4]=64 regs; 12 frag loads per 24 MMAs = 2.0
// ratio vs R11's 1.5 — targets the measured L1=60% / tensor=49% imbalance).
// 2 CTAs/SM via __launch_bounds__(256,2); peak live regs ~96.
// Sync batched LDG->STS, stride-72 smem.
// ===========================================================================
#define BKC 64
#define NCH2 (DM / BKC) // 16
#define SSTRIDE 72
// As_h 64x72 | As_l 64x72 | Bs_h 256x72 | Bs_l 256x72 (bf16)
#define GEMM_SMEM ((64 + 64 + 256 + 256) * SSTRIDE * 2) // 92160 B

__global__ __launch_bounds__(256, 2) void gemm_tc(
    const __nv_bfloat16* __restrict__ Ahg, const __nv_bfloat16* __restrict__ Alg,
    const __nv_bfloat16* __restrict__ Bhg, const __nv_bfloat16* __restrict__ Blg,
    float* __restrict__ C)
{
    extern __shared__ char smem[];
    __nv_bfloat16* As_h = reinterpret_cast<__nv_bfloat16*>(smem);
    __nv_bfloat16* As_l = As_h + 64 * SSTRIDE;
    __nv_bfloat16* Bs_h = As_l + 64 * SSTRIDE;
    __nv_bfloat16* Bs_l = Bs_h + 256 * SSTRIDE;

    const int tid = threadIdx.x;
    const int wid = tid >> 5;
    const int wm = wid >> 2; // 0..1 -> 32-row block
    const int wn = wid & 3;  // 0..3 -> 64-col block
    const int bm = blockIdx.y * 64, bn = blockIdx.x * 256;

    const __nv_bfloat16* pAh = Ahg + (size_t)bm * DM;
    const __nv_bfloat16* pAl = Alg + (size_t)bm * DM;
    const __nv_bfloat16* pBh = Bhg + (size_t)bn * DM;
    const __nv_bfloat16* pBl = Blg + (size_t)bn * DM;

    wmma::fragment<wmma::accumulator, 16, 16, 16, float> acc[2][4];
#pragma unroll
    for (int i = 0; i < 2; i++)
#pragma unroll
        for (int j = 0; j < 4; j++)
            wmma::fill_fragment(acc[i][j], 0.0f);

#pragma unroll 1
    for (int c = 0; c < NCH2; c++) {
        const int kc = c * BKC;
        // ---- sync load: 5120 16B units, 20 per thread ----
#pragma unroll
        for (int p = 0; p < 20; p++) {
            const __nv_bfloat16* src;
            __nv_bfloat16* dst;
            int local;
            if (p < 2)       { src = pAh; dst = As_h; local = p * 256 + tid; }
            else if (p < 4)  { src = pAl; dst = As_l; local = (p - 2) * 256 + tid; }
            else if (p < 12) { src = pBh; dst = Bs_h; local = (p - 4) * 256 + tid; }
            else             { src = pBl; dst = Bs_l; local = (p - 12) * 256 + tid; }
            const int row = local >> 3, u = local & 7;
            uint4 val = *reinterpret_cast<const uint4*>(
                src + (size_t)row * DM + kc + u * 8);
            *reinterpret_cast<uint4*>(dst + row * SSTRIDE + u * 8) = val;
        }
        __syncthreads();

#pragma unroll
        for (int ks = 0; ks < 4; ks++) {
            wmma::fragment<wmma::matrix_a, 16, 16, 16, __nv_bfloat16, wmma::row_major> ah[2];
            wmma::fragment<wmma::matrix_b, 16, 16, 16, __nv_bfloat16, wmma::col_major> bh[4];
#pragma unroll
            for (int i = 0; i < 2; i++)
                wmma::load_matrix_sync(ah[i], As_h + (wm * 32 + i * 16) * SSTRIDE + ks * 16, SSTRIDE);
#pragma unroll
            for (int j = 0; j < 4; j++)
                wmma::load_matrix_sync(bh[j], Bs_h + (wn * 64 + j * 16) * SSTRIDE + ks * 16, SSTRIDE);
            // hh
#pragma unroll
            for (int i = 0; i < 2; i++)
#pragma unroll
                for (int j = 0; j < 4; j++)
                    wmma::mma_sync(acc[i][j], ah[i], bh[j], acc[i][j]);
            // lh: Al x Bh (al transient; bh still live)
            {
                wmma::fragment<wmma::matrix_a, 16, 16, 16, __nv_bfloat16, wmma::row_major> al[2];
#pragma unroll
                for (int i = 0; i < 2; i++)
                    wmma::load_matrix_sync(al[i], As_l + (wm * 32 + i * 16) * SSTRIDE + ks * 16, SSTRIDE);
#pragma unroll
                for (int i = 0; i < 2; i++)
#pragma unroll
                    for (int j = 0; j < 4; j++)
                        wmma::mma_sync(acc[i][j], al[i], bh[j], acc[i][j]);
            }
            // hl: Ah x Bl (bl transient; ah still live)
            {
                wmma::fragment<wmma::matrix_b, 16, 16, 16, __nv_bfloat16, wmma::col_major> bl[4];
#pragma unroll
                for (int j = 0; j < 4; j++)
                    wmma::load_matrix_sync(bl[j], Bs_l + (wn * 64 + j * 16) * SSTRIDE + ks * 16, SSTRIDE);
#pragma unroll
                for (int i = 0; i < 2; i++)
#pragma unroll
                    for (int j = 0; j < 4; j++)
                        wmma::mma_sync(acc[i][j], ah[i], bl[j], acc[i][j]);
            }
        }
        __syncthreads();
    }

#pragma unroll
    for (int i = 0; i < 2; i++)
#pragma unroll
        for (int j = 0; j < 4; j++)
            wmma::store_matrix_sync(
                C + (size_t)(bm + wm * 32 + i * 16) * DM + bn + wn * 64 + j * 16,
                acc[i][j], DM, wmma::mem_row_major);
}

// ===========================================================================
// Chunked local attention on TENSOR CORES (R13-exact; 530us measured era).
// 256 threads, smem overlay -> 92160 B -> 2 CTAs/SM.
// ===========================================================================
#define AT_STRIDE 72   // bf16
#define SS_STRIDE 132  // fp32
#define P_STRIDE 136   // bf16
#define O_STRIDE 68    // fp32

#define QH_OFF 0
#define QL_OFF (64 * AT_STRIDE * 2)
#define KH_OFF (2 * 64 * AT_STRIDE * 2)
#define KL_OFF (KH_OFF + 128 * AT_STRIDE * 2)
#define VH_OFF (KL_OFF + 128 * AT_STRIDE * 2)
#define VL_OFF (VH_OFF + 128 * AT_STRIDE * 2)
#define ATTN_SMEM_BYTES (VL_OFF + 128 * AT_STRIDE * 2) // 92160
#define PH_OFF 0
#define PL_OFF (64 * P_STRIDE * 2)

__global__ __launch_bounds__(256, 2) void attn_kernel(
    const float* __restrict__ q, const float* __restrict__ k,
    const float* __restrict__ v, __nv_bfloat16* __restrict__ oh,
    __nv_bfloat16* __restrict__ ol)
{
    extern __shared__ char sm[];
    __nv_bfloat16* Qh = reinterpret_cast<__nv_bfloat16*>(sm + QH_OFF);
    __nv_bfloat16* Ql = reinterpret_cast<__nv_bfloat16*>(sm + QL_OFF);
    __nv_bfloat16* Kh = reinterpret_cast<__nv_bfloat16*>(sm + KH_OFF);
    __nv_bfloat16* Kl = reinterpret_cast<__nv_bfloat16*>(sm + KL_OFF);
    __nv_bfloat16* Vh = reinterpret_cast<__nv_bfloat16*>(sm + VH_OFF);
    __nv_bfloat16* Vl = reinterpret_cast<__nv_bfloat16*>(sm + VL_OFF);
    float* Ss = reinterpret_cast<float*>(sm);
    __nv_bfloat16* Ph = reinterpret_cast<__nv_bfloat16*>(sm + PH_OFF);
    __nv_bfloat16* Pl = reinterpret_cast<__nv_bfloat16*>(sm + PL_OFF);
    float* Os = reinterpret_cast<float*>(sm);

    const int bid = blockIdx.x;
    const int rtile = bid & 3;
    const int head = (bid >> 2) & 15;
    const int chunk = (bid >> 6) & (NCHUNK - 1);
    const int b = bid >> 11;

    const int tid = threadIdx.x;
    const int wid = tid >> 5;
    const int wm = wid >> 2;
    const int wn = wid & 3;
    const int c0 = rtile * 64 - 64;
    const size_t base = ((size_t)(b * SEQ + chunk * 256)) * DM + head * HD;

    for (int idx = tid; idx < 64 * 16; idx += 256) {
        int row = idx >> 4;
        int c = (idx & 15) << 2;
        float4 val = *reinterpret_cast<const float4*>(
            q + base + (size_t)(rtile * 64 + row) * DM + c);
        float f[4] = {val.x * 0.125f, val.y * 0.125f, val.z * 0.125f, val.w * 0.125f};
#pragma unroll
        for (int t = 0; t < 4; t++) {
            __nv_bfloat16 h, l;
            split1(f[t], h, l);
            Qh[row * AT_STRIDE + c + t] = h;
            Ql[row * AT_STRIDE + c + t] = l;
        }
    }
    for (int idx = tid; idx < 128 * 16; idx += 256) {
        int row = idx >> 4;
        int c = (idx & 15) << 2;
        int jc = c0 + row;
        float4 kv = make_float4(0.f, 0.f, 0.f, 0.f);
        float4 vv = make_float4(0.f, 0.f, 0.f, 0.f);
        if (jc >= 0) {
            kv = *reinterpret_cast<const float4*>(k + base + (size_t)jc * DM + c);
            vv = *reinterpret_cast<const float4*>(v + base + (size_t)jc * DM + c);
        }
        float kf[4] = {kv.x, kv.y, kv.z, kv.w};
        float vf[4] = {vv.x, vv.y, vv.z, vv.w};
#pragma unroll
        for (int t = 0; t < 4; t++) {
            __nv_bfloat16 h, l;
            split1(kf[t], h, l);
            Kh[row * AT_STRIDE + c + t] = h;
            Kl[row * AT_STRIDE + c + t] = l;
            split1(vf[t], h, l);
            Vh[row * AT_STRIDE + c + t] = h;
            Vl[row * AT_STRIDE + c + t] = l;
        }
    }
    __syncthreads();

    wmma::fragment<wmma::accumulator, 16, 16, 16, float> sacc[2][2];
#pragma unroll
    for (int i = 0; i < 2; i++)
#pragma unroll
        for (int j = 0; j < 2; j++)
            wmma::fill_fragment(sacc[i][j], 0.0f);

#pragma unroll
    for (int ks = 0; ks < 4; ks++) {
        wmma::fragment<wmma::matrix_a, 16, 16, 16, __nv_bfloat16, wmma::row_major> ah[2];
        wmma::fragment<wmma::matrix_b, 16, 16, 16, __nv_bfloat16, wmma::col_major> bh[2];
#pragma unroll
        for (int i = 0; i < 2; i++)
            wmma::load_matrix_sync(ah[i], Qh + (wm * 32 + i * 16) * AT_STRIDE + ks * 16, AT_STRIDE);
#pragma unroll
        for (int j = 0; j < 2; j++)
            wmma::load_matrix_sync(bh[j], Kh + (wn * 32 + j * 16) * AT_STRIDE + ks * 16, AT_STRIDE);
#pragma unroll
        for (int i = 0; i < 2; i++)
#pragma unroll
            for (int j = 0; j < 2; j++)
                wmma::mma_sync(sacc[i][j], ah[i], bh[j], sacc[i][j]);
        {
            wmma::fragment<wmma::matrix_a, 16, 16, 16, __nv_bfloat16, wmma::row_major> al[2];
#pragma unroll
            for (int i = 0; i < 2; i++)
                wmma::load_matrix_sync(al[i], Ql + (wm * 32 + i * 16) * AT_STRIDE + ks * 16, AT_STRIDE);
#pragma unroll
            for (int i = 0; i < 2; i++)
#pragma unroll
                for (int j = 0; j < 2; j++)
                    wmma::mma_sync(sacc[i][j], al[i], bh[j], sacc[i][j]);
        }
        {
            wmma::fragment<wmma::matrix_b, 16, 16, 16, __nv_bfloat16, wmma::col_major> bl[2];
#pragma unroll
            for (int j = 0; j < 2; j++)
                wmma::load_matrix_sync(bl[j], Kl + (wn * 32 + j * 16) * AT_STRIDE + ks * 16, AT_STRIDE);
#pragma unroll
            for (int i = 0; i < 2; i++)
#pragma unroll
                for (int j = 0; j < 2; j++)
                    wmma::mma_sync(sacc[i][j], ah[i], bl[j], sacc[i][j]);
        }
    }
    __syncthreads();

#pragma unroll
    for (int i = 0; i < 2; i++)
#pragma unroll
        for (int j = 0; j < 2; j++)
            wmma::store_matrix_sync(
                Ss + (wm * 32 + i * 16) * SS_STRIDE + wn * 32 + j * 16,
                sacc[i][j], SS_STRIDE, wmma::mem_row_major);
    __syncthreads();

    {
        const int i = tid >> 2;
        const int sub = tid & 3;
        const int lo = (rtile == 0) ? 64 : i;
        const int hi = i + 64;
        float* row = Ss + i * SS_STRIDE + sub * 32;
        const int jbase = sub * 32;

        float m = -1e30f;
#pragma unroll
        for (int jj = 0; jj < 32; jj++) {
            int j = jbase + jj;
            if (j >= lo && j <= hi) m = fmaxf(m, row[jj]);
        }
        m = fmaxf(m, __shfl_xor_sync(0xffffffffu, m, 1));
        m = fmaxf(m, __shfl_xor_sync(0xffffffffu, m, 2));

        float s = 0.f;
#pragma unroll
        for (int jj = 0; jj < 32; jj++) {
            int j = jbase + jj;
            float e = 0.f;
            if (j >= lo && j <= hi) {
                e = __expf(row[jj] - m);
                s += e;
            }
            row[jj] = e;
        }
        s += __shfl_xor_sync(0xffffffffu, s, 1);
        s += __shfl_xor_sync(0xffffffffu, s, 2);
        float inv = 1.0f / s;
#pragma unroll
        for (int jj = 0; jj < 32; jj++) row[jj] *= inv;
    }
    __syncthreads();

    {
        const int row = tid >> 2;
        const int jb = (tid & 3) * 32;
        float pr[32];
#pragma unroll
        for (int t = 0; t < 32; t++) pr[t] = Ss[row * SS_STRIDE + jb + t];
        __syncthreads();
#pragma unroll
        for (int t = 0; t < 32; t++) {
            __nv_bfloat16 h, l;
            split1(pr[t], h, l);
            Ph[row * P_STRIDE + jb + t] = h;
            Pl[row * P_STRIDE + jb + t] = l;
        }
    }
    __syncthreads();

    wmma::fragment<wmma::accumulator, 16, 16, 16, float> oacc[2];
#pragma unroll
    for (int i = 0; i < 2; i++) wmma::fill_fragment(oacc[i], 0.0f);

#pragma unroll
    for (int ks = 0; ks < 8; ks++) {
        wmma::fragment<wmma::matrix_a, 16, 16, 16, __nv_bfloat16, wmma::row_major> pah[2];
        wmma::fragment<wmma::matrix_b, 16, 16, 16, __nv_bfloat16, wmma::row_major> vbh;
#pragma unroll
        for (int i = 0; i < 2; i++)
            wmma::load_matrix_sync(pah[i], Ph + (wm * 32 + i * 16) * P_STRIDE + ks * 16, P_STRIDE);
        wmma::load_matrix_sync(vbh, Vh + (ks * 16) * AT_STRIDE + wn * 16, AT_STRIDE);
#pragma unroll
        for (int i = 0; i < 2; i++)
            wmma::mma_sync(oacc[i], pah[i], vbh, oacc[i]);
        {
            wmma::fragment<wmma::matrix_b, 16, 16, 16, __nv_bfloat16, wmma::row_major> vbl;
            wmma::load_matrix_sync(vbl, Vl + (ks * 16) * AT_STRIDE + wn * 16, AT_STRIDE);
#pragma unroll
            for (int i = 0; i < 2; i++)
                wmma::mma_sync(oacc[i], pah[i], vbl, oacc[i]);
        }
        {
            wmma::fragment<wmma::matrix_a, 16, 16, 16, __nv_bfloat16, wmma::row_major> pal[2];
#pragma unroll
            for (int i = 0; i < 2; i++)
                wmma::load_matrix_sync(pal[i], Pl + (wm * 32 + i * 16) * P_STRIDE + ks * 16, P_STRIDE);
            wmma::fragment<wmma::matrix_b, 16, 16, 16, __nv_bfloat16, wmma::row_major> vbh2;
            wmma::load_matrix_sync(vbh2, Vh + (ks * 16) * AT_STRIDE + wn * 16, AT_STRIDE);
#pragma unroll
            for (int i = 0; i < 2; i++)
                wmma::mma_sync(oacc[i], pal[i], vbh2, oacc[i]);
        }
    }
    __syncthreads();

#pragma unroll
    for (int i = 0; i < 2; i++)
        wmma::store_matrix_sync(Os + (wm * 32 + i * 16) * O_STRIDE + wn * 16,
                                oacc[i], O_STRIDE, wmma::mem_row_major);
    __syncthreads();

    {
        const int row = tid >> 2;
        const int d0 = (tid & 3) * 16;
        size_t off = base + (size_t)(rtile * 64 + row) * DM + d0;
#pragma unroll
        for (int d2 = 0; d2 < 8; d2++) {
            float f0 = Os[row * O_STRIDE + d0 + d2 * 2 + 0];
            float f1 = Os[row * O_STRIDE + d0 + d2 * 2 + 1];
            __nv_bfloat16 h0, h1, l0, l1;
            split1(f0, h0, l0);
            split1(f1, h1, l1);
            __nv_bfloat162 hp; hp.x = h0; hp.y = h1;
            __nv_bfloat162 lp; lp.x = l0; lp.y = l1;
            *reinterpret_cast<__nv_bfloat162*>(oh + off + d2 * 2) = hp;
            *reinterpret_cast<__nv_bfloat162*>(ol + off + d2 * 2) = lp;
        }
    }
}

// ===========================================================================
// kernel_launch
// ===========================================================================
extern "C" void kernel_launch(void* const* d_in, const int* in_sizes, int n_in,
                              void* d_out, int out_size)
{
    (void)in_sizes; (void)n_in; (void)out_size;
    const float* x  = (const float*)d_in[0];
    const float* Wq = (const float*)d_in[1];
    const float* Wk = (const float*)d_in[2];
    const float* Wv = (const float*)d_in[3];
    const float* Wo = (const float*)d_in[4];
    float* out = (float*)d_out;

    float *q, *k, *v;
    __nv_bfloat16 *ah, *al, *wh, *wl;
    cudaGetSymbolAddress((void**)&q, g_q);
    cudaGetSymbolAddress((void**)&k, g_k);
    cudaGetSymbolAddress((void**)&v, g_v);
    cudaGetSymbolAddress((void**)&ah, g_ah);
    cudaGetSymbolAddress((void**)&al, g_al);
    cudaGetSymbolAddress((void**)&wh, g_wh);
    cudaGetSymbolAddress((void**)&wl, g_wl);

    cudaFuncSetAttribute(gemm_tc, cudaFuncAttributeMaxDynamicSharedMemorySize,
                         GEMM_SMEM);
    cudaFuncSetAttribute(attn_kernel, cudaFuncAttributeMaxDynamicSharedMemorySize,
                         ATTN_SMEM_BYTES);

    // 1) split x into bf16 hi/lo
    splitx_kernel<<<(MTOT * DM / 4) / 256, 256>>>(
        (const float4*)x, (__nv_bfloat162*)ah, (__nv_bfloat162*)al);

    // 2) transpose+split all four weights (one launch)
    dim3 wgrid(DM / 32, DM / 32, 4);
    dim3 wblk(32, 8);
    wtrans_kernel<<<wgrid, wblk>>>(Wq, Wk, Wv, Wo, wh, wl);

    // 3) Q/K/V projections
    dim3 ggrid(DM / 256, MTOT / 64); // (4, 512)
    gemm_tc<<<ggrid, 256, GEMM_SMEM>>>(ah, al, wh + 0 * (size_t)DM * DM, wl + 0 * (size_t)DM * DM, q);
    gemm_tc<<<ggrid, 256, GEMM_SMEM>>>(ah, al, wh + 1 * (size_t)DM * DM, wl + 1 * (size_t)DM * DM, k);
    gemm_tc<<<ggrid, 256, GEMM_SMEM>>>(ah, al, wh + 2 * (size_t)DM * DM, wl + 2 * (size_t)DM * DM, v);

    // 4) attention on tensor cores (writes bf16 hi/lo into ah/al)
    attn_kernel<<<BATCH * NCHUNK * NH * 4, 256, ATTN_SMEM_BYTES>>>(q, k, v, ah, al);

    // 5) output projection
    gemm_tc<<<ggrid, 256, GEMM_SMEM>>>(ah, al, wh + 3 * (size_t)DM * DM, wl + 3 * (size_t)DM * DM, out);
}

// round 15
// speedup vs baseline: 1.5863x; 1.0552x over previous
#include <cuda_runtime.h>
#include <cuda_bf16.h>
#include <mma.h>
#include <cstdint>

using namespace nvcuda;

// ---------------- problem constants ----------------
#define BATCH 4
#define SEQ 8192
#define DM 1024
#define NH 16
#define HD 64
#define NCHUNK 32
#define MTOT (BATCH * SEQ) // 32768

// ---------------- scratch (device globals; no allocs) ----------------
__device__ float g_q[MTOT * DM];
__device__ float g_k[MTOT * DM];
__device__ float g_v[MTOT * DM];
__device__ __nv_bfloat16 g_ah[MTOT * DM]; // hi split of x, later of attn-out
__device__ __nv_bfloat16 g_al[MTOT * DM]; // lo split
__device__ __nv_bfloat16 g_wh[4 * DM * DM]; // transposed weights hi (q,k,v,o)
__device__ __nv_bfloat16 g_wl[4 * DM * DM]; // transposed weights lo

__device__ __forceinline__ void split1(float x, __nv_bfloat16& h, __nv_bfloat16& l) {
    h = __float2bfloat16_rn(x);
    l = __float2bfloat16_rn(x - __bfloat162float(h));
}

// ===========================================================================
// prep: split fp32 -> bf16 hi/lo
// ===========================================================================
__global__ __launch_bounds__(256) void splitx_kernel(
    const float4* __restrict__ in, __nv_bfloat162* __restrict__ h,
    __nv_bfloat162* __restrict__ l)
{
    size_t i = (size_t)blockIdx.x * 256 + threadIdx.x;
    float4 v = in[i];
    __nv_bfloat16 h0, h1, h2, h3, l0, l1, l2, l3;
    split1(v.x, h0, l0); split1(v.y, h1, l1);
    split1(v.z, h2, l2); split1(v.w, h3, l3);
    __nv_bfloat162 a; a.x = h0; a.y = h1;
    __nv_bfloat162 b; b.x = h2; b.y = h3;
    __nv_bfloat162 c; c.x = l0; c.y = l1;
    __nv_bfloat162 d; d.x = l2; d.y = l3;
    h[2 * i] = a; h[2 * i + 1] = b;
    l[2 * i] = c; l[2 * i + 1] = d;
}

// ===========================================================================
// prep: W[K,N] fp32 -> Wt[N,K] bf16 hi/lo, 4 mats in one launch (blockIdx.z)
// ===========================================================================
__global__ __launch_bounds__(256) void wtrans_kernel(
    const float* __restrict__ W0, const float* __restrict__ W1,
    const float* __restrict__ W2, const float* __restrict__ W3,
    __nv_bfloat16* __restrict__ th, __nv_bfloat16* __restrict__ tl)
{
    __shared__ float tile[32][33];
    const int mat = blockIdx.z;
    const float* W = (mat == 0) ? W0 : (mat == 1) ? W1 : (mat == 2) ? W2 : W3;
    __nv_bfloat16* thm = th + (size_t)mat * DM * DM;
    __nv_bfloat16* tlm = tl + (size_t)mat * DM * DM;

    const int n0 = blockIdx.x * 32, k0 = blockIdx.y * 32;
    const int tx = threadIdx.x, ty = threadIdx.y;
    for (int r = ty; r < 32; r += 8)
        tile[r][tx] = W[(size_t)(k0 + r) * DM + n0 + tx];
    __syncthreads();
    for (int r = ty; r < 32; r += 8) {
        float v = tile[tx][r];
        __nv_bfloat16 h, l;
        split1(v, h, l);
        size_t o = (size_t)(n0 + r) * DM + k0 + tx;
        thm[o] = h;
        tlm[o] = l;
    }
}

// ===========================================================================
// GEMM: R14 mainloop EXACTLY (tile 64x256, warp tile 32x64, ratio 2.0,
// 2 CTAs/SM, 626us/launch measured). Multi-matrix dispatch added:
// mat = blockIdx.x >> 2, bn = (blockIdx.x & 3) * 256. One launch covers QKV.
// ===========================================================================
#define BKC 64
#define NCH2 (DM / BKC) // 16
#define SSTRIDE 72
#define GEMM_SMEM ((64 + 64 + 256 + 256) * SSTRIDE * 2) // 92160 B

__global__ __launch_bounds__(256, 2) void gemm_tc(
    const __nv_bfloat16* __restrict__ Ahg, const __nv_bfloat16* __restrict__ Alg,
    const __nv_bfloat16* __restrict__ Whg, const __nv_bfloat16* __restrict__ Wlg,
    float* __restrict__ C0, float* __restrict__ C1, float* __restrict__ C2)
{
    extern __shared__ char smem[];
    __nv_bfloat16* As_h = reinterpret_cast<__nv_bfloat16*>(smem);
    __nv_bfloat16* As_l = As_h + 64 * SSTRIDE;
    __nv_bfloat16* Bs_h = As_l + 64 * SSTRIDE;
    __nv_bfloat16* Bs_l = Bs_h + 256 * SSTRIDE;

    const int tid = threadIdx.x;
    const int wid = tid >> 5;
    const int wm = wid >> 2; // 0..1 -> 32-row block
    const int wn = wid & 3;  // 0..3 -> 64-col block
    const int mat = blockIdx.x >> 2;
    const int bn = (blockIdx.x & 3) * 256;
    const int bm = blockIdx.y * 64;

    float* C = (mat == 0) ? C0 : (mat == 1) ? C1 : C2;

    const __nv_bfloat16* pAh = Ahg + (size_t)bm * DM;
    const __nv_bfloat16* pAl = Alg + (size_t)bm * DM;
    const __nv_bfloat16* pBh = Whg + (size_t)mat * DM * DM + (size_t)bn * DM;
    const __nv_bfloat16* pBl = Wlg + (size_t)mat * DM * DM + (size_t)bn * DM;

    wmma::fragment<wmma::accumulator, 16, 16, 16, float> acc[2][4];
#pragma unroll
    for (int i = 0; i < 2; i++)
#pragma unroll
        for (int j = 0; j < 4; j++)
            wmma::fill_fragment(acc[i][j], 0.0f);

#pragma unroll 1
    for (int c = 0; c < NCH2; c++) {
        const int kc = c * BKC;
#pragma unroll
        for (int p = 0; p < 20; p++) {
            const __nv_bfloat16* src;
            __nv_bfloat16* dst;
            int local;
            if (p < 2)       { src = pAh; dst = As_h; local = p * 256 + tid; }
            else if (p < 4)  { src = pAl; dst = As_l; local = (p - 2) * 256 + tid; }
            else if (p < 12) { src = pBh; dst = Bs_h; local = (p - 4) * 256 + tid; }
            else             { src = pBl; dst = Bs_l; local = (p - 12) * 256 + tid; }
            const int row = local >> 3, u = local & 7;
            uint4 val = *reinterpret_cast<const uint4*>(
                src + (size_t)row * DM + kc + u * 8);
            *reinterpret_cast<uint4*>(dst + row * SSTRIDE + u * 8) = val;
        }
        __syncthreads();

#pragma unroll
        for (int ks = 0; ks < 4; ks++) {
            wmma::fragment<wmma::matrix_a, 16, 16, 16, __nv_bfloat16, wmma::row_major> ah[2];
            wmma::fragment<wmma::matrix_b, 16, 16, 16, __nv_bfloat16, wmma::col_major> bh[4];
#pragma unroll
            for (int i = 0; i < 2; i++)
                wmma::load_matrix_sync(ah[i], As_h + (wm * 32 + i * 16) * SSTRIDE + ks * 16, SSTRIDE);
#pragma unroll
            for (int j = 0; j < 4; j++)
                wmma::load_matrix_sync(bh[j], Bs_h + (wn * 64 + j * 16) * SSTRIDE + ks * 16, SSTRIDE);
            // hh
#pragma unroll
            for (int i = 0; i < 2; i++)
#pragma unroll
                for (int j = 0; j < 4; j++)
                    wmma::mma_sync(acc[i][j], ah[i], bh[j], acc[i][j]);
            // lh: Al x Bh (al transient; bh still live)
            {
                wmma::fragment<wmma::matrix_a, 16, 16, 16, __nv_bfloat16, wmma::row_major> al[2];
#pragma unroll
                for (int i = 0; i < 2; i++)
                    wmma::load_matrix_sync(al[i], As_l + (wm * 32 + i * 16) * SSTRIDE + ks * 16, SSTRIDE);
#pragma unroll
                for (int i = 0; i < 2; i++)
#pragma unroll
                    for (int j = 0; j < 4; j++)
                        wmma::mma_sync(acc[i][j], al[i], bh[j], acc[i][j]);
            }
            // hl: Ah x Bl (bl transient; ah still live)
            {
                wmma::fragment<wmma::matrix_b, 16, 16, 16, __nv_bfloat16, wmma::col_major> bl[4];
#pragma unroll
                for (int j = 0; j < 4; j++)
                    wmma::load_matrix_sync(bl[j], Bs_l + (wn * 64 + j * 16) * SSTRIDE + ks * 16, SSTRIDE);
#pragma unroll
                for (int i = 0; i < 2; i++)
#pragma unroll
                    for (int j = 0; j < 4; j++)
                        wmma::mma_sync(acc[i][j], ah[i], bl[j], acc[i][j]);
            }
        }
        __syncthreads();
    }

#pragma unroll
    for (int i = 0; i < 2; i++)
#pragma unroll
        for (int j = 0; j < 4; j++)
            wmma::store_matrix_sync(
                C + (size_t)(bm + wm * 32 + i * 16) * DM + bn + wn * 64 + j * 16,
                acc[i][j], DM, wmma::mem_row_major);
}

// ===========================================================================
// Chunked local attention on TENSOR CORES (R13/R14-exact).
// 256 threads, smem overlay -> 92160 B -> 2 CTAs/SM.
// ===========================================================================
#define AT_STRIDE 72   // bf16
#define SS_STRIDE 132  // fp32
#define P_STRIDE 136   // bf16
#define O_STRIDE 68    // fp32

#define QH_OFF 0
#define QL_OFF (64 * AT_STRIDE * 2)
#define KH_OFF (2 * 64 * AT_STRIDE * 2)
#define KL_OFF (KH_OFF + 128 * AT_STRIDE * 2)
#define VH_OFF (KL_OFF + 128 * AT_STRIDE * 2)
#define VL_OFF (VH_OFF + 128 * AT_STRIDE * 2)
#define ATTN_SMEM_BYTES (VL_OFF + 128 * AT_STRIDE * 2) // 92160
#define PH_OFF 0
#define PL_OFF (64 * P_STRIDE * 2)

__global__ __launch_bounds__(256, 2) void attn_kernel(
    const float* __restrict__ q, const float* __restrict__ k,
    const float* __restrict__ v, __nv_bfloat16* __restrict__ oh,
    __nv_bfloat16* __restrict__ ol)
{
    extern __shared__ char sm[];
    __nv_bfloat16* Qh = reinterpret_cast<__nv_bfloat16*>(sm + QH_OFF);
    __nv_bfloat16* Ql = reinterpret_cast<__nv_bfloat16*>(sm + QL_OFF);
    __nv_bfloat16* Kh = reinterpret_cast<__nv_bfloat16*>(sm + KH_OFF);
    __nv_bfloat16* Kl = reinterpret_cast<__nv_bfloat16*>(sm + KL_OFF);
    __nv_bfloat16* Vh = reinterpret_cast<__nv_bfloat16*>(sm + VH_OFF);
    __nv_bfloat16* Vl = reinterpret_cast<__nv_bfloat16*>(sm + VL_OFF);
    float* Ss = reinterpret_cast<float*>(sm);
    __nv_bfloat16* Ph = reinterpret_cast<__nv_bfloat16*>(sm + PH_OFF);
    __nv_bfloat16* Pl = reinterpret_cast<__nv_bfloat16*>(sm + PL_OFF);
    float* Os = reinterpret_cast<float*>(sm);

    const int bid = blockIdx.x;
    const int rtile = bid & 3;
    const int head = (bid >> 2) & 15;
    const int chunk = (bid >> 6) & (NCHUNK - 1);
    const int b = bid >> 11;

    const int tid = threadIdx.x;
    const int wid = tid >> 5;
    const int wm = wid >> 2;
    const int wn = wid & 3;
    const int c0 = rtile * 64 - 64;
    const size_t base = ((size_t)(b * SEQ + chunk * 256)) * DM + head * HD;

    for (int idx = tid; idx < 64 * 16; idx += 256) {
        int row = idx >> 4;
        int c = (idx & 15) << 2;
        float4 val = *reinterpret_cast<const float4*>(
            q + base + (size_t)(rtile * 64 + row) * DM + c);
        float f[4] = {val.x * 0.125f, val.y * 0.125f, val.z * 0.125f, val.w * 0.125f};
#pragma unroll
        for (int t = 0; t < 4; t++) {
            __nv_bfloat16 h, l;
            split1(f[t], h, l);
            Qh[row * AT_STRIDE + c + t] = h;
            Ql[row * AT_STRIDE + c + t] = l;
        }
    }
    for (int idx = tid; idx < 128 * 16; idx += 256) {
        int row = idx >> 4;
        int c = (idx & 15) << 2;
        int jc = c0 + row;
        float4 kv = make_float4(0.f, 0.f, 0.f, 0.f);
        float4 vv = make_float4(0.f, 0.f, 0.f, 0.f);
        if (jc >= 0) {
            kv = *reinterpret_cast<const float4*>(k + base + (size_t)jc * DM + c);
            vv = *reinterpret_cast<const float4*>(v + base + (size_t)jc * DM + c);
        }
        float kf[4] = {kv.x, kv.y, kv.z, kv.w};
        float vf[4] = {vv.x, vv.y, vv.z, vv.w};
#pragma unroll
        for (int t = 0; t < 4; t++) {
            __nv_bfloat16 h, l;
            split1(kf[t], h, l);
            Kh[row * AT_STRIDE + c + t] = h;
            Kl[row * AT_STRIDE + c + t] = l;
            split1(vf[t], h, l);
            Vh[row * AT_STRIDE + c + t] = h;
            Vl[row * AT_STRIDE + c + t] = l;
        }
    }
    __syncthreads();

    wmma::fragment<wmma::accumulator, 16, 16, 16, float> sacc[2][2];
#pragma unroll
    for (int i = 0; i < 2; i++)
#pragma unroll
        for (int j = 0; j < 2; j++)
            wmma::fill_fragment(sacc[i][j], 0.0f);

#pragma unroll
    for (int ks = 0; ks < 4; ks++) {
        wmma::fragment<wmma::matrix_a, 16, 16, 16, __nv_bfloat16, wmma::row_major> ah[2];
        wmma::fragment<wmma::matrix_b, 16, 16, 16, __nv_bfloat16, wmma::col_major> bh[2];
#pragma unroll
        for (int i = 0; i < 2; i++)
            wmma::load_matrix_sync(ah[i], Qh + (wm * 32 + i * 16) * AT_STRIDE + ks * 16, AT_STRIDE);
#pragma unroll
        for (int j = 0; j < 2; j++)
            wmma::load_matrix_sync(bh[j], Kh + (wn * 32 + j * 16) * AT_STRIDE + ks * 16, AT_STRIDE);
#pragma unroll
        for (int i = 0; i < 2; i++)
#pragma unroll
            for (int j = 0; j < 2; j++)
                wmma::mma_sync(sacc[i][j], ah[i], bh[j], sacc[i][j]);
        {
            wmma::fragment<wmma::matrix_a, 16, 16, 16, __nv_bfloat16, wmma::row_major> al[2];
#pragma unroll
            for (int i = 0; i < 2; i++)
                wmma::load_matrix_sync(al[i], Ql + (wm * 32 + i * 16) * AT_STRIDE + ks * 16, AT_STRIDE);
#pragma unroll
            for (int i = 0; i < 2; i++)
#pragma unroll
                for (int j = 0; j < 2; j++)
                    wmma::mma_sync(sacc[i][j], al[i], bh[j], sacc[i][j]);
        }
        {
            wmma::fragment<wmma::matrix_b, 16, 16, 16, __nv_bfloat16, wmma::col_major> bl[2];
#pragma unroll
            for (int j = 0; j < 2; j++)
                wmma::load_matrix_sync(bl[j], Kl + (wn * 32 + j * 16) * AT_STRIDE + ks * 16, AT_STRIDE);
#pragma unroll
            for (int i = 0; i < 2; i++)
#pragma unroll
                for (int j = 0; j < 2; j++)
                    wmma::mma_sync(sacc[i][j], ah[i], bl[j], sacc[i][j]);
        }
    }
    __syncthreads();

#pragma unroll
    for (int i = 0; i < 2; i++)
#pragma unroll
        for (int j = 0; j < 2; j++)
            wmma::store_matrix_sync(
                Ss + (wm * 32 + i * 16) * SS_STRIDE + wn * 32 + j * 16,
                sacc[i][j], SS_STRIDE, wmma::mem_row_major);
    __syncthreads();

    {
        const int i = tid >> 2;
        const int sub = tid & 3;
        const int lo = (rtile == 0) ? 64 : i;
        const int hi = i + 64;
        float* row = Ss + i * SS_STRIDE + sub * 32;
        const int jbase = sub * 32;

        float m = -1e30f;
#pragma unroll
        for (int jj = 0; jj < 32; jj++) {
            int j = jbase + jj;
            if (j >= lo && j <= hi) m = fmaxf(m, row[jj]);
        }
        m = fmaxf(m, __shfl_xor_sync(0xffffffffu, m, 1));
        m = fmaxf(m, __shfl_xor_sync(0xffffffffu, m, 2));

        float s = 0.f;
#pragma unroll
        for (int jj = 0; jj < 32; jj++) {
            int j = jbase + jj;
            float e = 0.f;
            if (j >= lo && j <= hi) {
                e = __expf(row[jj] - m);
                s += e;
            }
            row[jj] = e;
        }
        s += __shfl_xor_sync(0xffffffffu, s, 1);
        s += __shfl_xor_sync(0xffffffffu, s, 2);
        float inv = 1.0f / s;
#pragma unroll
        for (int jj = 0; jj < 32; jj++) row[jj] *= inv;
    }
    __syncthreads();

    {
        const int row = tid >> 2;
        const int jb = (tid & 3) * 32;
        float pr[32];
#pragma unroll
        for (int t = 0; t < 32; t++) pr[t] = Ss[row * SS_STRIDE + jb + t];
        __syncthreads();
#pragma unroll
        for (int t = 0; t < 32; t++) {
            __nv_bfloat16 h, l;
            split1(pr[t], h, l);
            Ph[row * P_STRIDE + jb + t] = h;
            Pl[row * P_STRIDE + jb + t] = l;
        }
    }
    __syncthreads();

    wmma::fragment<wmma::accumulator, 16, 16, 16, float> oacc[2];
#pragma unroll
    for (int i = 0; i < 2; i++) wmma::fill_fragment(oacc[i], 0.0f);

#pragma unroll
    for (int ks = 0; ks < 8; ks++) {
        wmma::fragment<wmma::matrix_a, 16, 16, 16, __nv_bfloat16, wmma::row_major> pah[2];
        wmma::fragment<wmma::matrix_b, 16, 16, 16, __nv_bfloat16, wmma::row_major> vbh;
#pragma unroll
        for (int i = 0; i < 2; i++)
            wmma::load_matrix_sync(pah[i], Ph + (wm * 32 + i * 16) * P_STRIDE + ks * 16, P_STRIDE);
        wmma::load_matrix_sync(vbh, Vh + (ks * 16) * AT_STRIDE + wn * 16, AT_STRIDE);
#pragma unroll
        for (int i = 0; i < 2; i++)
            wmma::mma_sync(oacc[i], pah[i], vbh, oacc[i]);
        {
            wmma::fragment<wmma::matrix_b, 16, 16, 16, __nv_bfloat16, wmma::row_major> vbl;
            wmma::load_matrix_sync(vbl, Vl + (ks * 16) * AT_STRIDE + wn * 16, AT_STRIDE);
#pragma unroll
            for (int i = 0; i < 2; i++)
                wmma::mma_sync(oacc[i], pah[i], vbl, oacc[i]);
        }
        {
            wmma::fragment<wmma::matrix_a, 16, 16, 16, __nv_bfloat16, wmma::row_major> pal[2];
#pragma unroll
            for (int i = 0; i < 2; i++)
                wmma::load_matrix_sync(pal[i], Pl + (wm * 32 + i * 16) * P_STRIDE + ks * 16, P_STRIDE);
            wmma::fragment<wmma::matrix_b, 16, 16, 16, __nv_bfloat16, wmma::row_major> vbh2;
            wmma::load_matrix_sync(vbh2, Vh + (ks * 16) * AT_STRIDE + wn * 16, AT_STRIDE);
#pragma unroll
            for (int i = 0; i < 2; i++)
                wmma::mma_sync(oacc[i], pal[i], vbh2, oacc[i]);
        }
    }
    __syncthreads();

#pragma unroll
    for (int i = 0; i < 2; i++)
        wmma::store_matrix_sync(Os + (wm * 32 + i * 16) * O_STRIDE + wn * 16,
                                oacc[i], O_STRIDE, wmma::mem_row_major);
    __syncthreads();

    {
        const int row = tid >> 2;
        const int d0 = (tid & 3) * 16;
        size_t off = base + (size_t)(rtile * 64 + row) * DM + d0;
#pragma unroll
        for (int d2 = 0; d2 < 8; d2++) {
            float f0 = Os[row * O_STRIDE + d0 + d2 * 2 + 0];
            float f1 = Os[row * O_STRIDE + d0 + d2 * 2 + 1];
            __nv_bfloat16 h0, h1, l0, l1;
            split1(f0, h0, l0);
            split1(f1, h1, l1);
            __nv_bfloat162 hp; hp.x = h0; hp.y = h1;
            __nv_bfloat162 lp; lp.x = l0; lp.y = l1;
            *reinterpret_cast<__nv_bfloat162*>(oh + off + d2 * 2) = hp;
            *reinterpret_cast<__nv_bfloat162*>(ol + off + d2 * 2) = lp;
        }
    }
}

// ===========================================================================
// kernel_launch
// ===========================================================================
extern "C" void kernel_launch(void* const* d_in, const int* in_sizes, int n_in,
                              void* d_out, int out_size)
{
    (void)in_sizes; (void)n_in; (void)out_size;
    const float* x  = (const float*)d_in[0];
    const float* Wq = (const float*)d_in[1];
    const float* Wk = (const float*)d_in[2];
    const float* Wv = (const float*)d_in[3];
    const float* Wo = (const float*)d_in[4];
    float* out = (float*)d_out;

    float *q, *k, *v;
    __nv_bfloat16 *ah, *al, *wh, *wl;
    cudaGetSymbolAddress((void**)&q, g_q);
    cudaGetSymbolAddress((void**)&k, g_k);
    cudaGetSymbolAddress((void**)&v, g_v);
    cudaGetSymbolAddress((void**)&ah, g_ah);
    cudaGetSymbolAddress((void**)&al, g_al);
    cudaGetSymbolAddress((void**)&wh, g_wh);
    cudaGetSymbolAddress((void**)&wl, g_wl);

    cudaFuncSetAttribute(gemm_tc, cudaFuncAttributeMaxDynamicSharedMemorySize,
                         GEMM_SMEM);
    cudaFuncSetAttribute(attn_kernel, cudaFuncAttributeMaxDynamicSharedMemorySize,
                         ATTN_SMEM_BYTES);

    // 1) split x into bf16 hi/lo
    splitx_kernel<<<(MTOT * DM / 4) / 256, 256>>>(
        (const float4*)x, (__nv_bfloat162*)ah, (__nv_bfloat162*)al);

    // 2) transpose+split all four weights (one launch)
    dim3 wgrid(DM / 32, DM / 32, 4);
    dim3 wblk(32, 8);
    wtrans_kernel<<<wgrid, wblk>>>(Wq, Wk, Wv, Wo, wh, wl);

    // 3) fused Q/K/V projection: grid.x = 3 mats x 4 n-tiles
    dim3 qkvgrid(12, MTOT / 64); // (12, 512)
    gemm_tc<<<qkvgrid, 256, GEMM_SMEM>>>(ah, al, wh, wl, q, k, v);

    // 4) attention on tensor cores (writes bf16 hi/lo into ah/al)
    attn_kernel<<<BATCH * NCHUNK * NH * 4, 256, ATTN_SMEM_BYTES>>>(q, k, v, ah, al);

    // 5) output projection (mat index 0 within its own base pointer)
    dim3 ogrid(4, MTOT / 64);
    gemm_tc<<<ogrid, 256, GEMM_SMEM>>>(ah, al, wh + 3 * (size_t)DM * DM,
                                       wl + 3 * (size_t)DM * DM, out, out, out);
}

// round 16
// speedup vs baseline: 1.6651x; 1.0497x over previous
#include <cuda_runtime.h>
#include <cuda_bf16.h>
#include <mma.h>
#include <cstdint>

using namespace nvcuda;

// ---------------- problem constants ----------------
#define BATCH 4
#define SEQ 8192
#define DM 1024
#define NH 16
#define HD 64
#define NCHUNK 32
#define MTOT (BATCH * SEQ) // 32768

// ---------------- scratch (device globals; no allocs) ----------------
__device__ float g_q[MTOT * DM];
__device__ float g_k[MTOT * DM];
__device__ float g_v[MTOT * DM];
__device__ __nv_bfloat16 g_ah[MTOT * DM]; // hi split of x, later of attn-out
__device__ __nv_bfloat16 g_al[MTOT * DM]; // lo split
__device__ __nv_bfloat16 g_wh[4 * DM * DM]; // transposed weights hi (q,k,v,o)
__device__ __nv_bfloat16 g_wl[4 * DM * DM]; // transposed weights lo

__device__ __forceinline__ void split1(float x, __nv_bfloat16& h, __nv_bfloat16& l) {
    h = __float2bfloat16_rn(x);
    l = __float2bfloat16_rn(x - __bfloat162float(h));
}

// pack 4 floats into hi-uint2 and lo-uint2 (4 bf16 each)
__device__ __forceinline__ void split4_pack(const float* f, uint2& hp, uint2& lp) {
    __nv_bfloat16 h0, h1, h2, h3, l0, l1, l2, l3;
    split1(f[0], h0, l0); split1(f[1], h1, l1);
    split1(f[2], h2, l2); split1(f[3], h3, l3);
    __nv_bfloat162 ha; ha.x = h0; ha.y = h1;
    __nv_bfloat162 hb; hb.x = h2; hb.y = h3;
    __nv_bfloat162 la; la.x = l0; la.y = l1;
    __nv_bfloat162 lb; lb.x = l2; lb.y = l3;
    hp.x = *reinterpret_cast<uint32_t*>(&ha);
    hp.y = *reinterpret_cast<uint32_t*>(&hb);
    lp.x = *reinterpret_cast<uint32_t*>(&la);
    lp.y = *reinterpret_cast<uint32_t*>(&lb);
}

// ===========================================================================
// prep: split fp32 -> bf16 hi/lo
// ===========================================================================
__global__ __launch_bounds__(256) void splitx_kernel(
    const float4* __restrict__ in, __nv_bfloat162* __restrict__ h,
    __nv_bfloat162* __restrict__ l)
{
    size_t i = (size_t)blockIdx.x * 256 + threadIdx.x;
    float4 v = in[i];
    float f[4] = {v.x, v.y, v.z, v.w};
    uint2 hp, lp;
    split4_pack(f, hp, lp);
    *reinterpret_cast<uint2*>(h + 2 * i) = hp;
    *reinterpret_cast<uint2*>(l + 2 * i) = lp;
}

// ===========================================================================
// prep: W[K,N] fp32 -> Wt[N,K] bf16 hi/lo, 4 mats in one launch (blockIdx.z)
// ===========================================================================
__global__ __launch_bounds__(256) void wtrans_kernel(
    const float* __restrict__ W0, const float* __restrict__ W1,
    const float* __restrict__ W2, const float* __restrict__ W3,
    __nv_bfloat16* __restrict__ th, __nv_bfloat16* __restrict__ tl)
{
    __shared__ float tile[32][33];
    const int mat = blockIdx.z;
    const float* W = (mat == 0) ? W0 : (mat == 1) ? W1 : (mat == 2) ? W2 : W3;
    __nv_bfloat16* thm = th + (size_t)mat * DM * DM;
    __nv_bfloat16* tlm = tl + (size_t)mat * DM * DM;

    const int n0 = blockIdx.x * 32, k0 = blockIdx.y * 32;
    const int tx = threadIdx.x, ty = threadIdx.y;
    for (int r = ty; r < 32; r += 8)
        tile[r][tx] = W[(size_t)(k0 + r) * DM + n0 + tx];
    __syncthreads();
    for (int r = ty; r < 32; r += 8) {
        float v = tile[tx][r];
        __nv_bfloat16 h, l;
        split1(v, h, l);
        size_t o = (size_t)(n0 + r) * DM + k0 + tx;
        thm[o] = h;
        tlm[o] = l;
    }
}

// ===========================================================================
// GEMM: R14/R15 mainloop EXACTLY (tile 64x256, warp tile 32x64, 2 CTAs/SM).
// Multi-matrix dispatch: mat = blockIdx.x >> 2, bn = (blockIdx.x & 3) * 256.
// ===========================================================================
#define BKC 64
#define NCH2 (DM / BKC) // 16
#define SSTRIDE 72
#define GEMM_SMEM ((64 + 64 + 256 + 256) * SSTRIDE * 2) // 92160 B

__global__ __launch_bounds__(256, 2) void gemm_tc(
    const __nv_bfloat16* __restrict__ Ahg, const __nv_bfloat16* __restrict__ Alg,
    const __nv_bfloat16* __restrict__ Whg, const __nv_bfloat16* __restrict__ Wlg,
    float* __restrict__ C0, float* __restrict__ C1, float* __restrict__ C2)
{
    extern __shared__ char smem[];
    __nv_bfloat16* As_h = reinterpret_cast<__nv_bfloat16*>(smem);
    __nv_bfloat16* As_l = As_h + 64 * SSTRIDE;
    __nv_bfloat16* Bs_h = As_l + 64 * SSTRIDE;
    __nv_bfloat16* Bs_l = Bs_h + 256 * SSTRIDE;

    const int tid = threadIdx.x;
    const int wid = tid >> 5;
    const int wm = wid >> 2;
    const int wn = wid & 3;
    const int mat = blockIdx.x >> 2;
    const int bn = (blockIdx.x & 3) * 256;
    const int bm = blockIdx.y * 64;

    float* C = (mat == 0) ? C0 : (mat == 1) ? C1 : C2;

    const __nv_bfloat16* pAh = Ahg + (size_t)bm * DM;
    const __nv_bfloat16* pAl = Alg + (size_t)bm * DM;
    const __nv_bfloat16* pBh = Whg + (size_t)mat * DM * DM + (size_t)bn * DM;
    const __nv_bfloat16* pBl = Wlg + (size_t)mat * DM * DM + (size_t)bn * DM;

    wmma::fragment<wmma::accumulator, 16, 16, 16, float> acc[2][4];
#pragma unroll
    for (int i = 0; i < 2; i++)
#pragma unroll
        for (int j = 0; j < 4; j++)
            wmma::fill_fragment(acc[i][j], 0.0f);

#pragma unroll 1
    for (int c = 0; c < NCH2; c++) {
        const int kc = c * BKC;
#pragma unroll
        for (int p = 0; p < 20; p++) {
            const __nv_bfloat16* src;
            __nv_bfloat16* dst;
            int local;
            if (p < 2)       { src = pAh; dst = As_h; local = p * 256 + tid; }
            else if (p < 4)  { src = pAl; dst = As_l; local = (p - 2) * 256 + tid; }
            else if (p < 12) { src = pBh; dst = Bs_h; local = (p - 4) * 256 + tid; }
            else             { src = pBl; dst = Bs_l; local = (p - 12) * 256 + tid; }
            const int row = local >> 3, u = local & 7;
            uint4 val = *reinterpret_cast<const uint4*>(
                src + (size_t)row * DM + kc + u * 8);
            *reinterpret_cast<uint4*>(dst + row * SSTRIDE + u * 8) = val;
        }
        __syncthreads();

#pragma unroll
        for (int ks = 0; ks < 4; ks++) {
            wmma::fragment<wmma::matrix_a, 16, 16, 16, __nv_bfloat16, wmma::row_major> ah[2];
            wmma::fragment<wmma::matrix_b, 16, 16, 16, __nv_bfloat16, wmma::col_major> bh[4];
#pragma unroll
            for (int i = 0; i < 2; i++)
                wmma::load_matrix_sync(ah[i], As_h + (wm * 32 + i * 16) * SSTRIDE + ks * 16, SSTRIDE);
#pragma unroll
            for (int j = 0; j < 4; j++)
                wmma::load_matrix_sync(bh[j], Bs_h + (wn * 64 + j * 16) * SSTRIDE + ks * 16, SSTRIDE);
#pragma unroll
            for (int i = 0; i < 2; i++)
#pragma unroll
                for (int j = 0; j < 4; j++)
                    wmma::mma_sync(acc[i][j], ah[i], bh[j], acc[i][j]);
            {
                wmma::fragment<wmma::matrix_a, 16, 16, 16, __nv_bfloat16, wmma::row_major> al[2];
#pragma unroll
                for (int i = 0; i < 2; i++)
                    wmma::load_matrix_sync(al[i], As_l + (wm * 32 + i * 16) * SSTRIDE + ks * 16, SSTRIDE);
#pragma unroll
                for (int i = 0; i < 2; i++)
#pragma unroll
                    for (int j = 0; j < 4; j++)
                        wmma::mma_sync(acc[i][j], al[i], bh[j], acc[i][j]);
            }
            {
                wmma::fragment<wmma::matrix_b, 16, 16, 16, __nv_bfloat16, wmma::col_major> bl[4];
#pragma unroll
                for (int j = 0; j < 4; j++)
                    wmma::load_matrix_sync(bl[j], Bs_l + (wn * 64 + j * 16) * SSTRIDE + ks * 16, SSTRIDE);
#pragma unroll
                for (int i = 0; i < 2; i++)
#pragma unroll
                    for (int j = 0; j < 4; j++)
                        wmma::mma_sync(acc[i][j], ah[i], bl[j], acc[i][j]);
            }
        }
        __syncthreads();
    }

#pragma unroll
    for (int i = 0; i < 2; i++)
#pragma unroll
        for (int j = 0; j < 4; j++)
            wmma::store_matrix_sync(
                C + (size_t)(bm + wm * 32 + i * 16) * DM + bn + wn * 64 + j * 16,
                acc[i][j], DM, wmma::mem_row_major);
}

// ===========================================================================
// Chunked local attention on tensor cores. R16 changes vs R15:
//  - packed STS.64 staging of Q/K/V hi/lo splits
//  - softmax fused with P-convert (exp values live in registers; no P
//    round-trip through fp32 smem)
//  - packed uint2 writeout
// ===========================================================================
#define AT_STRIDE 72   // bf16
#define SS_STRIDE 132  // fp32
#define P_STRIDE 136   // bf16
#define O_STRIDE 68    // fp32

#define QH_OFF 0
#define QL_OFF (64 * AT_STRIDE * 2)
#define KH_OFF (2 * 64 * AT_STRIDE * 2)
#define KL_OFF (KH_OFF + 128 * AT_STRIDE * 2)
#define VH_OFF (KL_OFF + 128 * AT_STRIDE * 2)
#define VL_OFF (VH_OFF + 128 * AT_STRIDE * 2)
#define ATTN_SMEM_BYTES (VL_OFF + 128 * AT_STRIDE * 2) // 92160
#define PH_OFF 0
#define PL_OFF (64 * P_STRIDE * 2)

__global__ __launch_bounds__(256, 2) void attn_kernel(
    const float* __restrict__ q, const float* __restrict__ k,
    const float* __restrict__ v, __nv_bfloat16* __restrict__ oh,
    __nv_bfloat16* __restrict__ ol)
{
    extern __shared__ char sm[];
    __nv_bfloat16* Qh = reinterpret_cast<__nv_bfloat16*>(sm + QH_OFF);
    __nv_bfloat16* Ql = reinterpret_cast<__nv_bfloat16*>(sm + QL_OFF);
    __nv_bfloat16* Kh = reinterpret_cast<__nv_bfloat16*>(sm + KH_OFF);
    __nv_bfloat16* Kl = reinterpret_cast<__nv_bfloat16*>(sm + KL_OFF);
    __nv_bfloat16* Vh = reinterpret_cast<__nv_bfloat16*>(sm + VH_OFF);
    __nv_bfloat16* Vl = reinterpret_cast<__nv_bfloat16*>(sm + VL_OFF);
    float* Ss = reinterpret_cast<float*>(sm);
    __nv_bfloat16* Ph = reinterpret_cast<__nv_bfloat16*>(sm + PH_OFF);
    __nv_bfloat16* Pl = reinterpret_cast<__nv_bfloat16*>(sm + PL_OFF);
    float* Os = reinterpret_cast<float*>(sm);

    const int bid = blockIdx.x;
    const int rtile = bid & 3;
    const int head = (bid >> 2) & 15;
    const int chunk = (bid >> 6) & (NCHUNK - 1);
    const int b = bid >> 11;

    const int tid = threadIdx.x;
    const int wid = tid >> 5;
    const int wm = wid >> 2;
    const int wn = wid & 3;
    const int c0 = rtile * 64 - 64;
    const size_t base = ((size_t)(b * SEQ + chunk * 256)) * DM + head * HD;

    // ---- stage Q (x1/8) with packed STS.64 ----
    for (int idx = tid; idx < 64 * 16; idx += 256) {
        int row = idx >> 4;
        int c = (idx & 15) << 2;
        float4 val = *reinterpret_cast<const float4*>(
            q + base + (size_t)(rtile * 64 + row) * DM + c);
        float f[4] = {val.x * 0.125f, val.y * 0.125f, val.z * 0.125f, val.w * 0.125f};
        uint2 hp, lp;
        split4_pack(f, hp, lp);
        *reinterpret_cast<uint2*>(Qh + row * AT_STRIDE + c) = hp;
        *reinterpret_cast<uint2*>(Ql + row * AT_STRIDE + c) = lp;
    }
    // ---- stage K, V with packed STS.64 ----
    for (int idx = tid; idx < 128 * 16; idx += 256) {
        int row = idx >> 4;
        int c = (idx & 15) << 2;
        int jc = c0 + row;
        float4 kv = make_float4(0.f, 0.f, 0.f, 0.f);
        float4 vv = make_float4(0.f, 0.f, 0.f, 0.f);
        if (jc >= 0) {
            kv = *reinterpret_cast<const float4*>(k + base + (size_t)jc * DM + c);
            vv = *reinterpret_cast<const float4*>(v + base + (size_t)jc * DM + c);
        }
        float kf[4] = {kv.x, kv.y, kv.z, kv.w};
        float vf[4] = {vv.x, vv.y, vv.z, vv.w};
        uint2 hp, lp;
        split4_pack(kf, hp, lp);
        *reinterpret_cast<uint2*>(Kh + row * AT_STRIDE + c) = hp;
        *reinterpret_cast<uint2*>(Kl + row * AT_STRIDE + c) = lp;
        split4_pack(vf, hp, lp);
        *reinterpret_cast<uint2*>(Vh + row * AT_STRIDE + c) = hp;
        *reinterpret_cast<uint2*>(Vl + row * AT_STRIDE + c) = lp;
    }
    __syncthreads();

    // ---- S = (Q/8) @ K^T ----
    wmma::fragment<wmma::accumulator, 16, 16, 16, float> sacc[2][2];
#pragma unroll
    for (int i = 0; i < 2; i++)
#pragma unroll
        for (int j = 0; j < 2; j++)
            wmma::fill_fragment(sacc[i][j], 0.0f);

#pragma unroll
    for (int ks = 0; ks < 4; ks++) {
        wmma::fragment<wmma::matrix_a, 16, 16, 16, __nv_bfloat16, wmma::row_major> ah[2];
        wmma::fragment<wmma::matrix_b, 16, 16, 16, __nv_bfloat16, wmma::col_major> bh[2];
#pragma unroll
        for (int i = 0; i < 2; i++)
            wmma::load_matrix_sync(ah[i], Qh + (wm * 32 + i * 16) * AT_STRIDE + ks * 16, AT_STRIDE);
#pragma unroll
        for (int j = 0; j < 2; j++)
            wmma::load_matrix_sync(bh[j], Kh + (wn * 32 + j * 16) * AT_STRIDE + ks * 16, AT_STRIDE);
#pragma unroll
        for (int i = 0; i < 2; i++)
#pragma unroll
            for (int j = 0; j < 2; j++)
                wmma::mma_sync(sacc[i][j], ah[i], bh[j], sacc[i][j]);
        {
            wmma::fragment<wmma::matrix_a, 16, 16, 16, __nv_bfloat16, wmma::row_major> al[2];
#pragma unroll
            for (int i = 0; i < 2; i++)
                wmma::load_matrix_sync(al[i], Ql + (wm * 32 + i * 16) * AT_STRIDE + ks * 16, AT_STRIDE);
#pragma unroll
            for (int i = 0; i < 2; i++)
#pragma unroll
                for (int j = 0; j < 2; j++)
                    wmma::mma_sync(sacc[i][j], al[i], bh[j], sacc[i][j]);
        }
        {
            wmma::fragment<wmma::matrix_b, 16, 16, 16, __nv_bfloat16, wmma::col_major> bl[2];
#pragma unroll
            for (int j = 0; j < 2; j++)
                wmma::load_matrix_sync(bl[j], Kl + (wn * 32 + j * 16) * AT_STRIDE + ks * 16, AT_STRIDE);
#pragma unroll
            for (int i = 0; i < 2; i++)
#pragma unroll
                for (int j = 0; j < 2; j++)
                    wmma::mma_sync(sacc[i][j], ah[i], bl[j], sacc[i][j]);
        }
    }
    __syncthreads(); // Q/K reads done -> overlay Ss

#pragma unroll
    for (int i = 0; i < 2; i++)
#pragma unroll
        for (int j = 0; j < 2; j++)
            wmma::store_matrix_sync(
                Ss + (wm * 32 + i * 16) * SS_STRIDE + wn * 32 + j * 16,
                sacc[i][j], SS_STRIDE, wmma::mem_row_major);
    __syncthreads();

    // ---- fused masked softmax + P split (exp values stay in registers) ----
    {
        const int i = tid >> 2;
        const int sub = tid & 3;
        const int lo = (rtile == 0) ? 64 : i;
        const int hi = i + 64;
        const int jbase = sub * 32;

        float pr[32];
#pragma unroll
        for (int jj = 0; jj < 32; jj++) pr[jj] = Ss[i * SS_STRIDE + jbase + jj];

        float m = -1e30f;
#pragma unroll
        for (int jj = 0; jj < 32; jj++) {
            int j = jbase + jj;
            if (j >= lo && j <= hi) m = fmaxf(m, pr[jj]);
        }
        m = fmaxf(m, __shfl_xor_sync(0xffffffffu, m, 1));
        m = fmaxf(m, __shfl_xor_sync(0xffffffffu, m, 2));

        float s = 0.f;
#pragma unroll
        for (int jj = 0; jj < 32; jj++) {
            int j = jbase + jj;
            float e = 0.f;
            if (j >= lo && j <= hi) {
                e = __expf(pr[jj] - m);
                s += e;
            }
            pr[jj] = e;
        }
        s += __shfl_xor_sync(0xffffffffu, s, 1);
        s += __shfl_xor_sync(0xffffffffu, s, 2);
        float inv = 1.0f / s;

        __syncthreads(); // all Ss reads complete -> safe to overlay Ph/Pl

#pragma unroll
        for (int t4 = 0; t4 < 8; t4++) {
            float f[4] = {pr[t4 * 4 + 0] * inv, pr[t4 * 4 + 1] * inv,
                          pr[t4 * 4 + 2] * inv, pr[t4 * 4 + 3] * inv};
            uint2 hp, lp;
            split4_pack(f, hp, lp);
            *reinterpret_cast<uint2*>(Ph + i * P_STRIDE + jbase + t4 * 4) = hp;
            *reinterpret_cast<uint2*>(Pl + i * P_STRIDE + jbase + t4 * 4) = lp;
        }
    }
    __syncthreads();

    // ---- O = P @ V (ph*vh + ph*vl + pl*vh) ----
    wmma::fragment<wmma::accumulator, 16, 16, 16, float> oacc[2];
#pragma unroll
    for (int i = 0; i < 2; i++) wmma::fill_fragment(oacc[i], 0.0f);

#pragma unroll
    for (int ks = 0; ks < 8; ks++) {
        wmma::fragment<wmma::matrix_a, 16, 16, 16, __nv_bfloat16, wmma::row_major> pah[2];
        wmma::fragment<wmma::matrix_b, 16, 16, 16, __nv_bfloat16, wmma::row_major> vbh;
#pragma unroll
        for (int i = 0; i < 2; i++)
            wmma::load_matrix_sync(pah[i], Ph + (wm * 32 + i * 16) * P_STRIDE + ks * 16, P_STRIDE);
        wmma::load_matrix_sync(vbh, Vh + (ks * 16) * AT_STRIDE + wn * 16, AT_STRIDE);
#pragma unroll
        for (int i = 0; i < 2; i++)
            wmma::mma_sync(oacc[i], pah[i], vbh, oacc[i]);
        {
            wmma::fragment<wmma::matrix_b, 16, 16, 16, __nv_bfloat16, wmma::row_major> vbl;
            wmma::load_matrix_sync(vbl, Vl + (ks * 16) * AT_STRIDE + wn * 16, AT_STRIDE);
#pragma unroll
            for (int i = 0; i < 2; i++)
                wmma::mma_sync(oacc[i], pah[i], vbl, oacc[i]);
        }
        {
            wmma::fragment<wmma::matrix_a, 16, 16, 16, __nv_bfloat16, wmma::row_major> pal[2];
#pragma unroll
            for (int i = 0; i < 2; i++)
                wmma::load_matrix_sync(pal[i], Pl + (wm * 32 + i * 16) * P_STRIDE + ks * 16, P_STRIDE);
            wmma::fragment<wmma::matrix_b, 16, 16, 16, __nv_bfloat16, wmma::row_major> vbh2;
            wmma::load_matrix_sync(vbh2, Vh + (ks * 16) * AT_STRIDE + wn * 16, AT_STRIDE);
#pragma unroll
            for (int i = 0; i < 2; i++)
                wmma::mma_sync(oacc[i], pal[i], vbh2, oacc[i]);
        }
    }
    __syncthreads(); // P/V reads done -> overlay Os

#pragma unroll
    for (int i = 0; i < 2; i++)
        wmma::store_matrix_sync(Os + (wm * 32 + i * 16) * O_STRIDE + wn * 16,
                                oacc[i], O_STRIDE, wmma::mem_row_major);
    __syncthreads();

    // ---- packed writeout: split O to bf16 hi/lo ----
    {
        const int row = tid >> 2;
        const int d0 = (tid & 3) * 16;
        size_t off = base + (size_t)(rtile * 64 + row) * DM + d0;
#pragma unroll
        for (int d4 = 0; d4 < 4; d4++) {
            float f[4];
#pragma unroll
            for (int t = 0; t < 4; t++)
                f[t] = Os[row * O_STRIDE + d0 + d4 * 4 + t];
            uint2 hp, lp;
            split4_pack(f, hp, lp);
            *reinterpret_cast<uint2*>(oh + off + d4 * 4) = hp;
            *reinterpret_cast<uint2*>(ol + off + d4 * 4) = lp;
        }
    }
}

// ===========================================================================
// kernel_launch
// ===========================================================================
extern "C" void kernel_launch(void* const* d_in, const int* in_sizes, int n_in,
                              void* d_out, int out_size)
{
    (void)in_sizes; (void)n_in; (void)out_size;
    const float* x  = (const float*)d_in[0];
    const float* Wq = (const float*)d_in[1];
    const float* Wk = (const float*)d_in[2];
    const float* Wv = (const float*)d_in[3];
    const float* Wo = (const float*)d_in[4];
    float* out = (float*)d_out;

    float *q, *k, *v;
    __nv_bfloat16 *ah, *al, *wh, *wl;
    cudaGetSymbolAddress((void**)&q, g_q);
    cudaGetSymbolAddress((void**)&k, g_k);
    cudaGetSymbolAddress((void**)&v, g_v);
    cudaGetSymbolAddress((void**)&ah, g_ah);
    cudaGetSymbolAddress((void**)&al, g_al);
    cudaGetSymbolAddress((void**)&wh, g_wh);
    cudaGetSymbolAddress((void**)&wl, g_wl);

    cudaFuncSetAttribute(gemm_tc, cudaFuncAttributeMaxDynamicSharedMemorySize,
                         GEMM_SMEM);
    cudaFuncSetAttribute(attn_kernel, cudaFuncAttributeMaxDynamicSharedMemorySize,
                         ATTN_SMEM_BYTES);

    // 1) split x into bf16 hi/lo
    splitx_kernel<<<(MTOT * DM / 4) / 256, 256>>>(
        (const float4*)x, (__nv_bfloat162*)ah, (__nv_bfloat162*)al);

    // 2) transpose+split all four weights (one launch)
    dim3 wgrid(DM / 32, DM / 32, 4);
    dim3 wblk(32, 8);
    wtrans_kernel<<<wgrid, wblk>>>(Wq, Wk, Wv, Wo, wh, wl);

    // 3) fused Q/K/V projection: grid.x = 3 mats x 4 n-tiles
    dim3 qkvgrid(12, MTOT / 64); // (12, 512)
    gemm_tc<<<qkvgrid, 256, GEMM_SMEM>>>(ah, al, wh, wl, q, k, v);

    // 4) attention on tensor cores (writes bf16 hi/lo into ah/al)
    attn_kernel<<<BATCH * NCHUNK * NH * 4, 256, ATTN_SMEM_BYTES>>>(q, k, v, ah, al);

    // 5) output projection
    dim3 ogrid(4, MTOT / 64);
    gemm_tc<<<ogrid, 256, GEMM_SMEM>>>(ah, al, wh + 3 * (size_t)DM * DM,
                                       wl + 3 * (size_t)DM * DM, out, out, out);
}